// round 1
// baseline (speedup 1.0000x reference)
#include <cuda_runtime.h>
#include <math.h>

#define QLEN   1024
#define MEMLEN 1024
#define KLEN   2048
#define BSZ    2
#define NH     16
#define DH     64
#define DM     1024

// ---------------- scratch (device .bss — no runtime allocation) ------------
// qkv : [klen*bsz=4096, 3*1024]   (Q cols 0..1023, K 1024..2047, V 2048..3071)
// rk  : [2048, 1024]
// S   : [32 (n*2+b), 1024, 2048]  AC scores, then attention probs (in place)
// BD  : [32, 1024, 2048]          BD_pre (unshifted)
// av  : [1024, 2, 1024]           attention output vectors
// ao  : [1024, 2, 1024]           after output projection
static constexpr long long OFF_QKV = 0;
static constexpr long long OFF_RK  = 12582912LL;                 // 4096*3072
static constexpr long long OFF_S   = OFF_RK + 2097152LL;         // +2048*1024
static constexpr long long OFF_BD  = OFF_S  + 67108864LL;        // +32*1024*2048
static constexpr long long OFF_AV  = OFF_BD + 67108864LL;
static constexpr long long OFF_AO  = OFF_AV + 2097152LL;
static constexpr long long SCRATCH_TOTAL = OFF_AO + 2097152LL;   // 153,092,096 floats

__device__ float g_scratch[SCRATCH_TOTAL];

// ---------------- generic NN GEMM: C = A[M,K] @ B[K,N] ---------------------
// Batched via blockIdx.z with batch index z = n*2 + b (zb = z&1, zn = z>>1).
// Null ext pointer => operand lives in g_scratch at the given offset.
template<int BM, int BN, int TM, int TN>
__global__ void __launch_bounds__(256) gemm_nn(
    const float* __restrict__ Aext, long long Aoff,
    const float* __restrict__ Bext, long long Boff,
    float* __restrict__ Cext, long long Coff,
    int K, int lda, int ldb, int ldc,
    long long sAb, long long sAn,
    long long sBb, long long sBn,
    long long sCb, long long sCn)
{
    constexpr int BK = 8;
    const int zb = blockIdx.z & 1;
    const int zn = blockIdx.z >> 1;

    const float* A = (Aext ? Aext : (const float*)g_scratch + Aoff) + (long long)zb * sAb + (long long)zn * sAn;
    const float* B = (Bext ? Bext : (const float*)g_scratch + Boff) + (long long)zb * sBb + (long long)zn * sBn;
    float*       C = (Cext ? Cext : g_scratch + Coff)               + (long long)zb * sCb + (long long)zn * sCn;

    __shared__ float As[BK][BM];
    __shared__ float Bs[BK][BN];

    const int tid  = threadIdx.x;
    const int row0 = blockIdx.y * BM;
    const int col0 = blockIdx.x * BN;
    constexpr int TCOLS = BN / TN;
    const int tr = tid / TCOLS;
    const int tc = tid % TCOLS;

    float acc[TM][TN];
    #pragma unroll
    for (int m = 0; m < TM; m++)
        #pragma unroll
        for (int n = 0; n < TN; n++) acc[m][n] = 0.0f;

    for (int kb = 0; kb < K; kb += BK) {
        // A tile BM x BK (transposed into smem)
        for (int e = tid; e < BM * BK / 4; e += 256) {
            const int r  = e / (BK / 4);
            const int c4 = e % (BK / 4);
            const float4 v = *(const float4*)(A + (long long)(row0 + r) * lda + kb + c4 * 4);
            As[c4*4+0][r] = v.x; As[c4*4+1][r] = v.y; As[c4*4+2][r] = v.z; As[c4*4+3][r] = v.w;
        }
        // B tile BK x BN
        for (int e = tid; e < BK * BN / 4; e += 256) {
            const int r  = e / (BN / 4);
            const int c4 = e % (BN / 4);
            *(float4*)&Bs[r][c4*4] = *(const float4*)(B + (long long)(kb + r) * ldb + col0 + c4 * 4);
        }
        __syncthreads();
        #pragma unroll
        for (int kk = 0; kk < BK; kk++) {
            float a[TM], b[TN];
            #pragma unroll
            for (int m = 0; m < TM; m++) a[m] = As[kk][tr * TM + m];
            #pragma unroll
            for (int n = 0; n < TN; n++) b[n] = Bs[kk][tc * TN + n];
            #pragma unroll
            for (int m = 0; m < TM; m++)
                #pragma unroll
                for (int n = 0; n < TN; n++)
                    acc[m][n] = fmaf(a[m], b[n], acc[m][n]);
        }
        __syncthreads();
    }

    #pragma unroll
    for (int m = 0; m < TM; m++)
        #pragma unroll
        for (int n = 0; n < TN; n++)
            C[(long long)(row0 + tr * TM + m) * ldc + col0 + tc * TN + n] = acc[m][n];
}

// ---------------- NT GEMM, K=64 fixed: C[i,j] = dot(A[i,:]+bias, B[j,:]) ----
__global__ void __launch_bounds__(256) gemm_nt64(
    long long Aoff, long long Boff,
    const float* __restrict__ bias,
    long long Coff,
    int lda, int ldb, int ldc,
    long long sAb, long long sAn,
    long long sBb, long long sBn,
    long long sCb, long long sCn)
{
    const int zb = blockIdx.z & 1;
    const int zn = blockIdx.z >> 1;

    const float* A = (const float*)g_scratch + Aoff + (long long)zb * sAb + (long long)zn * sAn;
    const float* B = (const float*)g_scratch + Boff + (long long)zb * sBb + (long long)zn * sBn;
    float*       C = g_scratch + Coff + (long long)zb * sCb + (long long)zn * sCn;
    bias += zn * 64;

    __shared__ float As[32][128];
    __shared__ float Bs[32][128];
    __shared__ float sb[64];

    const int tid  = threadIdx.x;
    const int row0 = blockIdx.y * 128;
    const int col0 = blockIdx.x * 128;
    const int tr = tid >> 4;
    const int tc = tid & 15;

    if (tid < 64) sb[tid] = bias[tid];
    __syncthreads();

    float acc[8][8];
    #pragma unroll
    for (int m = 0; m < 8; m++)
        #pragma unroll
        for (int n = 0; n < 8; n++) acc[m][n] = 0.0f;

    for (int kb = 0; kb < 64; kb += 32) {
        #pragma unroll
        for (int it = 0; it < 4; it++) {
            const int e  = tid + it * 256;
            const int rr = e >> 3;
            const int c  = (e & 7) * 4;
            const float4 va = *(const float4*)(A + (long long)(row0 + rr) * lda + kb + c);
            As[c+0][rr] = va.x + sb[kb+c+0];
            As[c+1][rr] = va.y + sb[kb+c+1];
            As[c+2][rr] = va.z + sb[kb+c+2];
            As[c+3][rr] = va.w + sb[kb+c+3];
            const float4 vb = *(const float4*)(B + (long long)(col0 + rr) * ldb + kb + c);
            Bs[c+0][rr] = vb.x; Bs[c+1][rr] = vb.y; Bs[c+2][rr] = vb.z; Bs[c+3][rr] = vb.w;
        }
        __syncthreads();
        #pragma unroll
        for (int kk = 0; kk < 32; kk++) {
            float a[8], b[8];
            #pragma unroll
            for (int m = 0; m < 8; m++) a[m] = As[kk][tr * 8 + m];
            #pragma unroll
            for (int n = 0; n < 8; n++) b[n] = Bs[kk][tc * 8 + n];
            #pragma unroll
            for (int m = 0; m < 8; m++)
                #pragma unroll
                for (int n = 0; n < 8; n++)
                    acc[m][n] = fmaf(a[m], b[n], acc[m][n]);
        }
        __syncthreads();
    }

    #pragma unroll
    for (int m = 0; m < 8; m++)
        #pragma unroll
        for (int n = 0; n < 8; n++)
            C[(long long)(row0 + tr * 8 + m) * ldc + col0 + tc * 8 + n] = acc[m][n];
}

// ---------------- shift + mask + softmax (in place over S) -----------------
// score[i,j] = (AC[i,j] + BD_pre[i, j - i + QLEN-1]) * scale  for j <= i+MEMLEN
__global__ void __launch_bounds__(256) softmax_kernel()
{
    const int i = blockIdx.x;      // query row
    const int z = blockIdx.y;      // n*2 + b
    float*       srow = g_scratch + OFF_S  + (long long)z * QLEN * KLEN + (long long)i * KLEN;
    const float* brow = g_scratch + OFF_BD + (long long)z * QLEN * KLEN + (long long)i * KLEN;
    const int limit = i + MEMLEN;  // inclusive
    const int tid = threadIdx.x;

    float v[8];
    float lmax = -1e30f;
    #pragma unroll
    for (int u = 0; u < 8; u++) {
        const int j = tid + u * 256;
        if (j <= limit) {
            const float val = (srow[j] + brow[j - i + (QLEN - 1)]) * 0.125f;
            v[u] = val;
            lmax = fmaxf(lmax, val);
        } else {
            v[u] = -3.0e38f;
        }
    }
    __shared__ float red[256];
    red[tid] = lmax; __syncthreads();
    for (int s = 128; s; s >>= 1) { if (tid < s) red[tid] = fmaxf(red[tid], red[tid + s]); __syncthreads(); }
    const float m = red[0];
    __syncthreads();

    float lsum = 0.0f;
    #pragma unroll
    for (int u = 0; u < 8; u++) {
        const float e = expf(v[u] - m);   // masked lanes underflow to exactly 0
        v[u] = e; lsum += e;
    }
    red[tid] = lsum; __syncthreads();
    for (int s = 128; s; s >>= 1) { if (tid < s) red[tid] += red[tid + s]; __syncthreads(); }
    const float inv = 1.0f / red[0];

    #pragma unroll
    for (int u = 0; u < 8; u++)
        srow[tid + u * 256] = v[u] * inv;
}

// ---------------- residual + LayerNorm --------------------------------------
__global__ void __launch_bounds__(256) ln_kernel(
    const float* __restrict__ w,
    const float* __restrict__ gamma,
    const float* __restrict__ beta,
    float* __restrict__ out)
{
    const int row = blockIdx.x;   // q*2 + b, 2048 rows
    const float* wr = w + (long long)row * DM;
    const float* ar = g_scratch + OFF_AO + (long long)row * DM;
    const int tid = threadIdx.x;

    float y[4];
    float s = 0.0f, s2 = 0.0f;
    #pragma unroll
    for (int u = 0; u < 4; u++) {
        const int c = tid + u * 256;
        y[u] = wr[c] + ar[c];
        s += y[u]; s2 += y[u] * y[u];
    }
    __shared__ float rs[256], rs2[256];
    rs[tid] = s; rs2[tid] = s2; __syncthreads();
    for (int st = 128; st; st >>= 1) {
        if (tid < st) { rs[tid] += rs[tid + st]; rs2[tid] += rs2[tid + st]; }
        __syncthreads();
    }
    const float mu   = rs[0]  * (1.0f / 1024.0f);
    const float var  = rs2[0] * (1.0f / 1024.0f) - mu * mu;
    const float rstd = rsqrtf(var + 1e-5f);
    #pragma unroll
    for (int u = 0; u < 4; u++) {
        const int c = tid + u * 256;
        out[(long long)row * DM + c] = (y[u] - mu) * rstd * gamma[c] + beta[c];
    }
}

// ---------------- launch ----------------------------------------------------
extern "C" void kernel_launch(void* const* d_in, const int* in_sizes, int n_in,
                              void* d_out, int out_size)
{
    (void)in_sizes; (void)n_in; (void)out_size;
    const float* w     = (const float*)d_in[0];   // [1024,2,1024]
    const float* r     = (const float*)d_in[1];   // [2048,1024]
    const float* rwb   = (const float*)d_in[2];   // [16,64]
    const float* rrb   = (const float*)d_in[3];   // [16,64]
    const float* mems  = (const float*)d_in[4];   // [1024,2,1024]
    /* d_in[5] = attn_mask (deterministic, unused) */
    const float* Wqkv  = (const float*)d_in[6];   // [1024,3072]
    const float* Wr    = (const float*)d_in[7];   // [1024,1024]
    const float* Wo    = (const float*)d_in[8];   // [1024,1024]
    const float* gamma = (const float*)d_in[9];
    const float* beta  = (const float*)d_in[10];
    float* out = (float*)d_out;

    // 1) QKV projection: cat = [mems; w] is contiguous -> two GEMMs
    gemm_nn<128,128,8,8><<<dim3(24,16,1),256>>>(mems,0, Wqkv,0, nullptr,OFF_QKV,
        1024, 1024,3072,3072, 0,0,0,0,0,0);
    gemm_nn<128,128,8,8><<<dim3(24,16,1),256>>>(w,0, Wqkv,0, nullptr,OFF_QKV + 2048LL*3072,
        1024, 1024,3072,3072, 0,0,0,0,0,0);

    // 2) R projection
    gemm_nn<128,128,8,8><<<dim3(8,16,1),256>>>(r,0, Wr,0, nullptr,OFF_RK,
        1024, 1024,1024,1024, 0,0,0,0,0,0);

    // 3) AC = (Q + rw_bias) @ K^T  per (b,n); z = n*2+b
    gemm_nt64<<<dim3(16,8,32),256>>>(
        OFF_QKV + 2048LL*3072,           // Q base (rows = last qlen)
        OFF_QKV + 1024,                  // K base
        rwb,
        OFF_S,
        6144, 6144, 2048,
        3072, 64,                        // A: +b*3072, +n*64
        3072, 64,                        // B: +b*3072, +n*64
        2097152LL, 4194304LL);           // C: +b*2M, +n*4M

    // 4) BD_pre = (Q + rr_bias) @ RK^T  per (b,n)  (RK shared across b)
    gemm_nt64<<<dim3(16,8,32),256>>>(
        OFF_QKV + 2048LL*3072,
        OFF_RK,
        rrb,
        OFF_BD,
        6144, 1024, 2048,
        3072, 64,
        0, 64,
        2097152LL, 4194304LL);

    // 5) shift + mask + softmax (in place in S)
    softmax_kernel<<<dim3(1024,32),256>>>();

    // 6) attn_vec = P @ V  per (b,n)
    gemm_nn<128,64,8,4><<<dim3(1,8,32),256>>>(
        nullptr, OFF_S,
        nullptr, OFF_QKV + 2048,         // V base
        nullptr, OFF_AV,
        2048, 2048, 6144, 2048,
        2097152LL, 4194304LL,            // A: +b*2M, +n*4M
        3072, 64,                        // B: +b*3072, +n*64
        1024, 64);                       // C: av[i, b, n*64+d], ldc=2048

    // 7) output projection: attn_out = attn_vec @ W_o
    gemm_nn<128,128,8,8><<<dim3(8,16,1),256>>>(
        nullptr, OFF_AV, Wo, 0, nullptr, OFF_AO,
        1024, 1024,1024,1024, 0,0,0,0,0,0);

    // 8) residual + LayerNorm
    ln_kernel<<<2048,256>>>(w, gamma, beta, out);
}

// round 3
// speedup vs baseline: 3.6651x; 3.6651x over previous
#include <cuda_runtime.h>
#include <cstdint>
#include <math.h>

#define QLEN   1024
#define MEMLEN 1024
#define KLEN   2048
#define DM     1024

// ======================= scratch ============================================
static constexpr long long OFF_QKV = 0;                         // [4096][3072]
static constexpr long long OFF_RK  = 12582912LL;                // [2048][1024]
static constexpr long long OFF_S   = OFF_RK + 2097152LL;        // [32][1024][2048]
static constexpr long long OFF_BD  = OFF_S  + 67108864LL;       // [32][1024][2048]
static constexpr long long OFF_AV  = OFF_BD + 67108864LL;       // [2048][1024]
static constexpr long long OFF_AO  = OFF_AV + 2097152LL;        // [2048][1024]
static constexpr long long SCRATCH_TOTAL = OFF_AO + 2097152LL;

__device__ float g_scratch[SCRATCH_TOTAL];

// ======================= helpers ============================================
__device__ __forceinline__ uint32_t f2tf(float f) {
    uint32_t u;
    asm("cvt.rna.tf32.f32 %0, %1;" : "=r"(u) : "f"(f));
    return u;
}

__device__ __forceinline__ void mma_tf32(float* c, const uint32_t* a, const uint32_t* b)
{
    asm volatile(
        "mma.sync.aligned.m16n8k8.row.col.f32.tf32.tf32.f32 "
        "{%0,%1,%2,%3}, {%4,%5,%6,%7}, {%8,%9}, {%0,%1,%2,%3};"
        : "+f"(c[0]), "+f"(c[1]), "+f"(c[2]), "+f"(c[3])
        : "r"(a[0]), "r"(a[1]), "r"(a[2]), "r"(a[3]), "r"(b[0]), "r"(b[1]));
}

// ======================= tensor-core GEMM (mma.sync tf32) ===================
// C[M, N] = A[M,K] @ op(B);  A is always m-major/k-contig ("row").
// BT=true : B gmem is n-major, k-contig  (NT gemm, e.g. scores vs K^T)
// BT=false: B gmem is k-major, n-contig  (NN gemm, weights / V)
// Batched over blockIdx.z (z = n*2 + b). Dual-pointer A handles [mems;w] concat.
// skipmode: 0 none; 1 skip tile if fully masked (AC); 2 skip if never read (BD_pre).
template<int BN, bool BT>
__global__ void __launch_bounds__(256) gemm_mma(
    const float* __restrict__ A, const float* __restrict__ A2, int split,
    int lda, long long sAb, long long sAn,
    const float* __restrict__ B, int ldb, long long sBb, long long sBn,
    float* __restrict__ C, int ldc, long long sCb, long long sCn,
    int K, const float* __restrict__ bias, int skipmode)
{
    constexpr int BM = 128, BK = 32, LDS = 36;        // 36-float rows: 16B aligned, conflict-free
    constexpr int WCOLS = (BN == 128) ? 4 : 2;
    constexpr int WROWS = 8 / WCOLS;
    constexpr int WM = BM / WROWS;                    // 64 or 32
    constexpr int WN = BN / WCOLS;                    // 32
    constexpr int MT = WM / 16;                       // 4 or 2
    constexpr int NT = WN / 8;                        // 4
    constexpr int ACH = 4;                            // A staging float4/thread
    constexpr int BCH = (BN == 128) ? 4 : 2;          // B staging float4/thread

    const int row0 = blockIdx.y * BM;
    const int col0 = blockIdx.x * BN;
    if (skipmode == 1 && col0 > row0 + (BM - 1) + MEMLEN) return;
    if (skipmode == 2 && col0 + (BN - 1) < (QLEN - 1) - (row0 + BM - 1)) return;

    __shared__ uint32_t As[BM][LDS];
    __shared__ uint32_t Bs[BN][LDS];

    const int tid  = threadIdx.x;
    const int wid  = tid >> 5;
    const int lane = tid & 31;
    const int grp  = lane >> 2;
    const int tig  = lane & 3;
    const int wr = wid / WCOLS, wc = wid % WCOLS;
    const int wm0 = wr * WM, wn0 = wc * WN;

    const int zb = blockIdx.z & 1, zn = blockIdx.z >> 1;
    A += (long long)zb * sAb + (long long)zn * sAn;
    if (A2) A2 += (long long)zb * sAb + (long long)zn * sAn;
    B += (long long)zb * sBb + (long long)zn * sBn;
    C += (long long)zb * sCb + (long long)zn * sCn;
    const float* bp = bias ? bias + zn * 64 : nullptr;

    float acc[MT][NT][4];
    #pragma unroll
    for (int m = 0; m < MT; m++)
        #pragma unroll
        for (int n = 0; n < NT; n++)
            #pragma unroll
            for (int q = 0; q < 4; q++) acc[m][n][q] = 0.0f;

    float4 areg[ACH], breg[BCH];

    auto load_regs = [&](int kb) {
        #pragma unroll
        for (int i = 0; i < ACH; i++) {
            const int e = i * 256 + tid;
            const int r = e >> 3, c4 = e & 7;
            const int grow = row0 + r;
            const float* ap = (A2 && grow >= split)
                              ? (A2 + (long long)(grow - split) * lda)
                              : (A  + (long long)grow * lda);
            float4 v = *(const float4*)(ap + kb + c4 * 4);
            if (bp) {
                const float* q = bp + kb + c4 * 4;
                v.x += q[0]; v.y += q[1]; v.z += q[2]; v.w += q[3];
            }
            areg[i] = v;
        }
        if (BT) {
            #pragma unroll
            for (int i = 0; i < BCH; i++) {
                const int e = i * 256 + tid;
                const int r = e >> 3, c4 = e & 7;
                breg[i] = *(const float4*)(B + (long long)(col0 + r) * ldb + kb + c4 * 4);
            }
        } else {
            #pragma unroll
            for (int i = 0; i < BCH; i++) {
                const int e  = i * 256 + tid;
                const int kk = e / (BN / 4), n4 = e % (BN / 4);
                breg[i] = *(const float4*)(B + (long long)(kb + kk) * ldb + col0 + n4 * 4);
            }
        }
    };

    auto store_regs = [&]() {
        #pragma unroll
        for (int i = 0; i < ACH; i++) {
            const int e = i * 256 + tid;
            const int r = e >> 3, c4 = e & 7;
            *(uint4*)&As[r][c4 * 4] = make_uint4(
                f2tf(areg[i].x), f2tf(areg[i].y), f2tf(areg[i].z), f2tf(areg[i].w));
        }
        if (BT) {
            #pragma unroll
            for (int i = 0; i < BCH; i++) {
                const int e = i * 256 + tid;
                const int r = e >> 3, c4 = e & 7;
                *(uint4*)&Bs[r][c4 * 4] = make_uint4(
                    f2tf(breg[i].x), f2tf(breg[i].y), f2tf(breg[i].z), f2tf(breg[i].w));
            }
        } else {
            #pragma unroll
            for (int i = 0; i < BCH; i++) {
                const int e  = i * 256 + tid;
                const int kk = e / (BN / 4), n4 = e % (BN / 4);
                Bs[n4 * 4 + 0][kk] = f2tf(breg[i].x);
                Bs[n4 * 4 + 1][kk] = f2tf(breg[i].y);
                Bs[n4 * 4 + 2][kk] = f2tf(breg[i].z);
                Bs[n4 * 4 + 3][kk] = f2tf(breg[i].w);
            }
        }
    };

    const int T = K >> 5;
    load_regs(0);
    store_regs();
    __syncthreads();

    for (int t = 0; t < T; t++) {
        if (t + 1 < T) load_regs((t + 1) * 32);     // gmem loads overlap mma

        #pragma unroll
        for (int ks = 0; ks < 4; ks++) {
            const int k = ks * 8 + tig;
            uint32_t af[MT][4], bf[NT][2];
            #pragma unroll
            for (int m = 0; m < MT; m++) {
                const int r = wm0 + m * 16 + grp;
                af[m][0] = As[r][k];     af[m][1] = As[r + 8][k];
                af[m][2] = As[r][k + 4]; af[m][3] = As[r + 8][k + 4];
            }
            #pragma unroll
            for (int n = 0; n < NT; n++) {
                const int nn = wn0 + n * 8 + grp;
                bf[n][0] = Bs[nn][k]; bf[n][1] = Bs[nn][k + 4];
            }
            #pragma unroll
            for (int m = 0; m < MT; m++)
                #pragma unroll
                for (int n = 0; n < NT; n++)
                    mma_tf32(acc[m][n], af[m], bf[n]);
        }
        __syncthreads();
        if (t + 1 < T) {
            store_regs();
            __syncthreads();
        }
    }

    #pragma unroll
    for (int m = 0; m < MT; m++) {
        const int r = row0 + wm0 + m * 16 + grp;
        #pragma unroll
        for (int n = 0; n < NT; n++) {
            const int c = col0 + wn0 + n * 8 + 2 * tig;
            *(float2*)(C + (long long)r * ldc + c)       = make_float2(acc[m][n][0], acc[m][n][1]);
            *(float2*)(C + (long long)(r + 8) * ldc + c) = make_float2(acc[m][n][2], acc[m][n][3]);
        }
    }
}

// ======================= shift + mask + softmax =============================
__global__ void __launch_bounds__(256) softmax_kernel()
{
    const int i = blockIdx.x;
    const int z = blockIdx.y;
    float*       srow = g_scratch + OFF_S  + (long long)z * QLEN * KLEN + (long long)i * KLEN;
    const float* brow = g_scratch + OFF_BD + (long long)z * QLEN * KLEN + (long long)i * KLEN;
    const int limit = i + MEMLEN;
    const int tid = threadIdx.x;

    float v[8];
    float lmax = -1e30f;
    #pragma unroll
    for (int u = 0; u < 8; u++) {
        const int j = tid + u * 256;
        if (j <= limit) {
            const float val = (srow[j] + brow[j - i + (QLEN - 1)]) * 0.125f;
            v[u] = val;
            lmax = fmaxf(lmax, val);
        } else {
            v[u] = -3.0e38f;
        }
    }
    __shared__ float red[256];
    red[tid] = lmax; __syncthreads();
    for (int s = 128; s; s >>= 1) { if (tid < s) red[tid] = fmaxf(red[tid], red[tid + s]); __syncthreads(); }
    const float m = red[0];
    __syncthreads();

    float lsum = 0.0f;
    #pragma unroll
    for (int u = 0; u < 8; u++) {
        const float e = expf(v[u] - m);
        v[u] = e; lsum += e;
    }
    red[tid] = lsum; __syncthreads();
    for (int s = 128; s; s >>= 1) { if (tid < s) red[tid] += red[tid + s]; __syncthreads(); }
    const float inv = 1.0f / red[0];

    #pragma unroll
    for (int u = 0; u < 8; u++)
        srow[tid + u * 256] = v[u] * inv;
}

// ======================= residual + LayerNorm ===============================
__global__ void __launch_bounds__(256) ln_kernel(
    const float* __restrict__ w,
    const float* __restrict__ gamma,
    const float* __restrict__ beta,
    float* __restrict__ out)
{
    const int row = blockIdx.x;
    const float* wr = w + (long long)row * DM;
    const float* ar = g_scratch + OFF_AO + (long long)row * DM;
    const int tid = threadIdx.x;

    float y[4];
    float s = 0.0f, s2 = 0.0f;
    #pragma unroll
    for (int u = 0; u < 4; u++) {
        const int c = tid + u * 256;
        y[u] = wr[c] + ar[c];
        s += y[u]; s2 += y[u] * y[u];
    }
    __shared__ float rs[256], rs2[256];
    rs[tid] = s; rs2[tid] = s2; __syncthreads();
    for (int st = 128; st; st >>= 1) {
        if (tid < st) { rs[tid] += rs[tid + st]; rs2[tid] += rs2[tid + st]; }
        __syncthreads();
    }
    const float mu   = rs[0]  * (1.0f / 1024.0f);
    const float var  = rs2[0] * (1.0f / 1024.0f) - mu * mu;
    const float rstd = rsqrtf(var + 1e-5f);
    #pragma unroll
    for (int u = 0; u < 4; u++) {
        const int c = tid + u * 256;
        out[(long long)row * DM + c] = (y[u] - mu) * rstd * gamma[c] + beta[c];
    }
}

// ======================= launch =============================================
extern "C" void kernel_launch(void* const* d_in, const int* in_sizes, int n_in,
                              void* d_out, int out_size)
{
    (void)in_sizes; (void)n_in; (void)out_size;
    const float* w     = (const float*)d_in[0];   // [1024,2,1024]
    const float* r     = (const float*)d_in[1];   // [2048,1024]
    const float* rwb   = (const float*)d_in[2];   // [16,64]
    const float* rrb   = (const float*)d_in[3];   // [16,64]
    const float* mems  = (const float*)d_in[4];   // [1024,2,1024]
    /* d_in[5] = attn_mask (deterministic, unused) */
    const float* Wqkv  = (const float*)d_in[6];   // [1024,3072]
    const float* Wr    = (const float*)d_in[7];   // [1024,1024]
    const float* Wo    = (const float*)d_in[8];   // [1024,1024]
    const float* gamma = (const float*)d_in[9];
    const float* beta  = (const float*)d_in[10];
    float* out = (float*)d_out;

    float* g = nullptr;
    cudaGetSymbolAddress((void**)&g, g_scratch);

    // 1) QKV projection: cat=[mems;w] via dual A pointer (NN vs Wqkv)
    gemm_mma<128, false><<<dim3(24, 32, 1), 256>>>(
        mems, w, 2048, 1024, 0, 0,
        Wqkv, 3072, 0, 0,
        g + OFF_QKV, 3072, 0, 0, 1024, nullptr, 0);

    // 2) R projection (NN vs Wr)
    gemm_mma<128, false><<<dim3(8, 16, 1), 256>>>(
        r, nullptr, 0, 1024, 0, 0,
        Wr, 1024, 0, 0,
        g + OFF_RK, 1024, 0, 0, 1024, nullptr, 0);

    // 3) AC = (Q + rwb) @ K^T   (NT; z = n*2 + b; masked-tile skip)
    gemm_mma<128, true><<<dim3(16, 8, 32), 256>>>(
        g + OFF_QKV + 2048LL * 3072, nullptr, 0, 6144, 3072, 64,
        g + OFF_QKV + 1024,                      6144, 3072, 64,
        g + OFF_S, 2048, 2097152LL, 4194304LL, 64, rwb, 1);

    // 4) BD_pre = (Q + rrb) @ RK^T  (NT; unused-tile skip)
    gemm_mma<128, true><<<dim3(16, 8, 32), 256>>>(
        g + OFF_QKV + 2048LL * 3072, nullptr, 0, 6144, 3072, 64,
        g + OFF_RK,                              1024, 0,    64,
        g + OFF_BD, 2048, 2097152LL, 4194304LL, 64, rrb, 2);

    // 5) shift + mask + softmax (in place in S)
    softmax_kernel<<<dim3(1024, 32), 256>>>();

    // 6) attn_vec = P @ V  (NN; V read strided straight out of qkv)
    gemm_mma<64, false><<<dim3(1, 8, 32), 256>>>(
        g + OFF_S, nullptr, 0, 2048, 2097152LL, 4194304LL,
        g + OFF_QKV + 2048, 6144, 3072, 64,
        g + OFF_AV, 2048, 1024LL, 64LL, 2048, nullptr, 0);

    // 7) output projection (NN vs Wo)
    gemm_mma<128, false><<<dim3(8, 16, 1), 256>>>(
        g + OFF_AV, nullptr, 0, 1024, 0, 0,
        Wo, 1024, 0, 0,
        g + OFF_AO, 1024, 0, 0, 1024, nullptr, 0);

    // 8) residual + LayerNorm
    ln_kernel<<<2048, 256>>>(w, gamma, beta, out);
}

// round 4
// speedup vs baseline: 5.9299x; 1.6179x over previous
#include <cuda_runtime.h>
#include <cstdint>
#include <math.h>

#define QLEN   1024
#define MEMLEN 1024
#define KLEN   2048
#define DM     1024

// ======================= scratch ============================================
static constexpr long long OFF_QKV   = 0;                            // [4096][3072]
static constexpr long long OFF_RK    = 12582912LL;                   // [2048][1024]
static constexpr long long OFF_S     = OFF_RK    + 2097152LL;        // [32][1024][2048]
static constexpr long long OFF_BD    = OFF_S     + 67108864LL;       // [32][1024][2048]
static constexpr long long OFF_AV    = OFF_BD    + 67108864LL;       // [2048][1024]
static constexpr long long OFF_AO    = OFF_AV    + 2097152LL;        // [2048][1024]
static constexpr long long OFF_WQKVT = OFF_AO    + 2097152LL;        // [3072][1024]
static constexpr long long OFF_WRT   = OFF_WQKVT + 3145728LL;        // [1024][1024]
static constexpr long long OFF_WOT   = OFF_WRT   + 1048576LL;        // [1024][1024]
static constexpr long long OFF_VT    = OFF_WOT   + 1048576LL;        // [32][64][2048]
static constexpr long long OFF_ACB   = OFF_VT    + 4194304LL;        // [32][2048]
static constexpr long long OFF_BDB   = OFF_ACB   + 65536LL;          // [32][2048]
static constexpr long long SCRATCH_TOTAL = OFF_BDB + 65536LL;

__device__ float g_scratch[SCRATCH_TOTAL];

// ======================= helpers ============================================
__device__ __forceinline__ uint32_t smem_u32(const void* p) {
    uint32_t a;
    asm("{ .reg .u64 t; cvta.to.shared.u64 t, %1; cvt.u32.u64 %0, t; }" : "=r"(a) : "l"(p));
    return a;
}
__device__ __forceinline__ void cp16(uint32_t s, const void* g) {
    asm volatile("cp.async.cg.shared.global [%0], [%1], 16;" :: "r"(s), "l"(g));
}
__device__ __forceinline__ void cp_commit() {
    asm volatile("cp.async.commit_group;");
}
template<int N> __device__ __forceinline__ void cp_wait() {
    asm volatile("cp.async.wait_group %0;" :: "n"(N));
}
__device__ __forceinline__ void mma_tf32(float* c, const uint32_t* a, const uint32_t* b)
{
    asm volatile(
        "mma.sync.aligned.m16n8k8.row.col.f32.tf32.tf32.f32 "
        "{%0,%1,%2,%3}, {%4,%5,%6,%7}, {%8,%9}, {%0,%1,%2,%3};"
        : "+f"(c[0]), "+f"(c[1]), "+f"(c[2]), "+f"(c[3])
        : "r"(a[0]), "r"(a[1]), "r"(a[2]), "r"(a[3]), "r"(b[0]), "r"(b[1]));
}

// ======================= pipelined NT GEMM (cp.async + mma tf32) ============
// C[M,N] = A[M,K] @ B[N,K]^T ; both operands k-contiguous in gmem.
// A dual-pointer handles the [mems; w] concat. Batched over blockIdx.z (z=n*2+b).
// skipmode: 0 none; 1 skip fully-masked AC tiles; 2 skip never-read BD_pre tiles.
template<int BN>
__global__ void __launch_bounds__(256, 2) gemm_nt(
    const float* __restrict__ A, const float* __restrict__ A2, int split, int lda,
    long long sAb, long long sAn,
    const float* __restrict__ B, int ldb, long long sBb, long long sBn,
    float* __restrict__ C, int ldc, long long sCb, long long sCn,
    int K, int skipmode)
{
    constexpr int BM = 128, LDSW = 36;
    constexpr int STAGE_A = BM * LDSW;           // floats
    constexpr int STAGE_B = BN * LDSW;
    constexpr int STAGE   = STAGE_A + STAGE_B;
    constexpr int ACH = BM * 32 / (4 * 256);     // 4 float4 chunks / thread
    constexpr int BCH = BN * 32 / (4 * 256);     // 4 or 2
    constexpr int WCOLS = (BN == 128) ? 4 : 2;
    constexpr int WROWS = 8 / WCOLS;
    constexpr int WM = BM / WROWS, WN = BN / WCOLS;
    constexpr int MT = WM / 16, NT = WN / 8;

    const int row0 = blockIdx.y * BM;
    const int col0 = blockIdx.x * BN;
    if (skipmode == 1 && col0 > row0 + (BM - 1) + MEMLEN) return;
    if (skipmode == 2 && col0 + BN - 1 < (QLEN - 1) - (row0 + BM - 1)) return;

    extern __shared__ float smf[];
    const int tid = threadIdx.x, wid = tid >> 5, lane = tid & 31;
    const int grp = lane >> 2, tig = lane & 3;
    const int wr = wid / WCOLS, wc = wid % WCOLS;
    const int wm0 = wr * WM, wn0 = wc * WN;

    const int zb = blockIdx.z & 1, zn = blockIdx.z >> 1;
    A += (long long)zb * sAb + (long long)zn * sAn;
    if (A2) A2 += (long long)zb * sAb + (long long)zn * sAn;
    B += (long long)zb * sBb + (long long)zn * sBn;
    C += (long long)zb * sCb + (long long)zn * sCn;

    // per-thread staging map: element e = i*256+tid -> row lr+i*32, float4 col lc4
    const int lr = tid >> 3, lc4 = tid & 7;
    const float* aptr[ACH];
    #pragma unroll
    for (int i = 0; i < ACH; i++) {
        const int grow = row0 + lr + i * 32;
        const float* base = (A2 && grow >= split)
                            ? (A2 + (long long)(grow - split) * lda)
                            : (A  + (long long)grow * lda);
        aptr[i] = base + lc4 * 4;
    }
    const float* bptr[BCH];
    #pragma unroll
    for (int i = 0; i < BCH; i++)
        bptr[i] = B + (long long)(col0 + lr + i * 32) * ldb + lc4 * 4;

    const uint32_t s0   = smem_u32(smf);
    const uint32_t adst = (uint32_t)(lr * LDSW * 4 + lc4 * 16);
    const uint32_t bdst = (uint32_t)(STAGE_A * 4 + lr * LDSW * 4 + lc4 * 16);

    auto issue = [&](int s, int kb) {
        const uint32_t base = s0 + (uint32_t)s * (STAGE * 4);
        #pragma unroll
        for (int i = 0; i < ACH; i++)
            cp16(base + adst + (uint32_t)(i * 32 * LDSW * 4), aptr[i] + kb);
        #pragma unroll
        for (int i = 0; i < BCH; i++)
            cp16(base + bdst + (uint32_t)(i * 32 * LDSW * 4), bptr[i] + kb);
        cp_commit();
    };

    float acc[MT][NT][4];
    #pragma unroll
    for (int m = 0; m < MT; m++)
        #pragma unroll
        for (int n = 0; n < NT; n++)
            #pragma unroll
            for (int q = 0; q < 4; q++) acc[m][n][q] = 0.0f;

    const int T = K >> 5;
    issue(0, 0);
    if (T > 1) issue(1, 32); else cp_commit();

    int st = 0;
    for (int t = 0; t < T; t++) {
        cp_wait<1>();
        __syncthreads();

        const uint32_t* As = (const uint32_t*)smf + st * STAGE;
        const uint32_t* Bs = As + STAGE_A;

        #pragma unroll
        for (int ks = 0; ks < 4; ks++) {
            const int k = ks * 8 + tig;
            uint32_t af[MT][4], bf[NT][2];
            #pragma unroll
            for (int m = 0; m < MT; m++) {
                const int r = wm0 + m * 16 + grp;
                af[m][0] = As[r * LDSW + k];       af[m][1] = As[(r + 8) * LDSW + k];
                af[m][2] = As[r * LDSW + k + 4];   af[m][3] = As[(r + 8) * LDSW + k + 4];
            }
            #pragma unroll
            for (int n = 0; n < NT; n++) {
                const int nn = wn0 + n * 8 + grp;
                bf[n][0] = Bs[nn * LDSW + k];      bf[n][1] = Bs[nn * LDSW + k + 4];
            }
            #pragma unroll
            for (int m = 0; m < MT; m++)
                #pragma unroll
                for (int n = 0; n < NT; n++)
                    mma_tf32(acc[m][n], af[m], bf[n]);
        }

        const int tn = t + 2;
        if (tn < T) issue(tn == 2 ? 2 : (tn % 3), tn * 32); else cp_commit();
        st++; if (st == 3) st = 0;
    }

    #pragma unroll
    for (int m = 0; m < MT; m++) {
        const int r = row0 + wm0 + m * 16 + grp;
        #pragma unroll
        for (int n = 0; n < NT; n++) {
            const int c = col0 + wn0 + n * 8 + 2 * tig;
            *(float2*)(C + (long long)r * ldc + c)       = make_float2(acc[m][n][0], acc[m][n][1]);
            *(float2*)(C + (long long)(r + 8) * ldc + c) = make_float2(acc[m][n][2], acc[m][n][3]);
        }
    }
}

// ======================= transposes =========================================
__global__ void transpose_k(const float* __restrict__ src, float* __restrict__ dst,
                            int rows, int cols)
{
    __shared__ float t[32][33];
    const int c0 = blockIdx.x * 32, r0 = blockIdx.y * 32;
    for (int i = threadIdx.y; i < 32; i += 8)
        t[i][threadIdx.x] = src[(long long)(r0 + i) * cols + c0 + threadIdx.x];
    __syncthreads();
    for (int i = threadIdx.y; i < 32; i += 8)
        dst[(long long)(c0 + i) * rows + r0 + threadIdx.x] = t[threadIdx.x][i];
}

// VT[z][d][j] = qkv[(j*2+zb)*3072 + 2048 + zn*64 + d],  z = zn*2+zb
__global__ void vtrans_kernel(const float* __restrict__ qkv, float* __restrict__ vt)
{
    __shared__ float t[32][33];
    const int j0 = blockIdx.x * 32;
    const int d0 = blockIdx.y * 32;
    const int z  = blockIdx.z;
    const int zb = z & 1, zn = z >> 1;
    for (int i = threadIdx.y; i < 32; i += 8)
        t[i][threadIdx.x] =
            qkv[(long long)((j0 + i) * 2 + zb) * 3072 + 2048 + zn * 64 + d0 + threadIdx.x];
    __syncthreads();
    float* dst = vt + (long long)z * 64 * 2048;
    for (int i = threadIdx.y; i < 32; i += 8)
        dst[(long long)(d0 + i) * 2048 + j0 + threadIdx.x] = t[threadIdx.x][i];
}

// ======================= rank-1 bias dots ===================================
// acb[z][j] = rwb[zn] . K[z][j]    (kind 0)
// bdb[z][p] = rrb[zn] . RK[p][zn]  (kind 1)
__global__ void bias_dot(const float* __restrict__ rwb, const float* __restrict__ rrb)
{
    const int gw   = blockIdx.x * 8 + (threadIdx.x >> 5);
    const int lane = threadIdx.x & 31;
    const int kind = blockIdx.y;
    const int z = gw >> 11, j = gw & 2047;
    const int zb = z & 1, zn = z >> 1;
    const float* bias = (kind ? rrb : rwb) + zn * 64;
    const float* row = kind
        ? g_scratch + OFF_RK  + (long long)j * 1024 + zn * 64
        : g_scratch + OFF_QKV + 1024 + (long long)(j * 2 + zb) * 3072 + zn * 64;
    float s = row[lane] * bias[lane] + row[lane + 32] * bias[lane + 32];
    #pragma unroll
    for (int o = 16; o; o >>= 1) s += __shfl_xor_sync(0xffffffffu, s, o);
    if (lane == 0)
        g_scratch[(kind ? OFF_BDB : OFF_ACB) + (long long)z * 2048 + j] = s;
}

// ======================= shift + mask + softmax =============================
__global__ void __launch_bounds__(256) softmax_kernel()
{
    const int i = blockIdx.x;
    const int z = blockIdx.y;
    float*       srow = g_scratch + OFF_S  + (long long)z * QLEN * KLEN + (long long)i * KLEN;
    const float* brow = g_scratch + OFF_BD + (long long)z * QLEN * KLEN + (long long)i * KLEN;
    const float* acb  = g_scratch + OFF_ACB + (long long)z * 2048;
    const float* bdb  = g_scratch + OFF_BDB + (long long)z * 2048;
    const int limit = i + MEMLEN;
    const int tid = threadIdx.x;

    float v[8];
    float lmax = -1e30f;
    #pragma unroll
    for (int u = 0; u < 8; u++) {
        const int j = tid + u * 256;
        if (j <= limit) {
            const int p = j - i + (QLEN - 1);
            const float val = (srow[j] + acb[j] + brow[p] + bdb[p]) * 0.125f;
            v[u] = val;
            lmax = fmaxf(lmax, val);
        } else {
            v[u] = -3.0e38f;
        }
    }
    __shared__ float red[256];
    red[tid] = lmax; __syncthreads();
    for (int s = 128; s; s >>= 1) { if (tid < s) red[tid] = fmaxf(red[tid], red[tid + s]); __syncthreads(); }
    const float m = red[0];
    __syncthreads();

    float lsum = 0.0f;
    #pragma unroll
    for (int u = 0; u < 8; u++) {
        const float e = expf(v[u] - m);
        v[u] = e; lsum += e;
    }
    red[tid] = lsum; __syncthreads();
    for (int s = 128; s; s >>= 1) { if (tid < s) red[tid] += red[tid + s]; __syncthreads(); }
    const float inv = 1.0f / red[0];

    #pragma unroll
    for (int u = 0; u < 8; u++)
        srow[tid + u * 256] = v[u] * inv;
}

// ======================= residual + LayerNorm ===============================
__global__ void __launch_bounds__(256) ln_kernel(
    const float* __restrict__ w,
    const float* __restrict__ gamma,
    const float* __restrict__ beta,
    float* __restrict__ out)
{
    const int row = blockIdx.x;
    const float* wr = w + (long long)row * DM;
    const float* ar = g_scratch + OFF_AO + (long long)row * DM;
    const int tid = threadIdx.x;

    float y[4];
    float s = 0.0f, s2 = 0.0f;
    #pragma unroll
    for (int u = 0; u < 4; u++) {
        const int c = tid + u * 256;
        y[u] = wr[c] + ar[c];
        s += y[u]; s2 += y[u] * y[u];
    }
    __shared__ float rs[256], rs2[256];
    rs[tid] = s; rs2[tid] = s2; __syncthreads();
    for (int st = 128; st; st >>= 1) {
        if (tid < st) { rs[tid] += rs[tid + st]; rs2[tid] += rs2[tid + st]; }
        __syncthreads();
    }
    const float mu   = rs[0]  * (1.0f / 1024.0f);
    const float var  = rs2[0] * (1.0f / 1024.0f) - mu * mu;
    const float rstd = rsqrtf(var + 1e-5f);
    #pragma unroll
    for (int u = 0; u < 4; u++) {
        const int c = tid + u * 256;
        out[(long long)row * DM + c] = (y[u] - mu) * rstd * gamma[c] + beta[c];
    }
}

// ======================= launch =============================================
extern "C" void kernel_launch(void* const* d_in, const int* in_sizes, int n_in,
                              void* d_out, int out_size)
{
    (void)in_sizes; (void)n_in; (void)out_size;
    const float* w     = (const float*)d_in[0];   // [1024,2,1024]
    const float* r     = (const float*)d_in[1];   // [2048,1024]
    const float* rwb   = (const float*)d_in[2];   // [16,64]
    const float* rrb   = (const float*)d_in[3];   // [16,64]
    const float* mems  = (const float*)d_in[4];   // [1024,2,1024]
    /* d_in[5] = attn_mask (deterministic, unused) */
    const float* Wqkv  = (const float*)d_in[6];   // [1024,3072]
    const float* Wr    = (const float*)d_in[7];   // [1024,1024]
    const float* Wo    = (const float*)d_in[8];   // [1024,1024]
    const float* gamma = (const float*)d_in[9];
    const float* beta  = (const float*)d_in[10];
    float* out = (float*)d_out;

    float* g = nullptr;
    cudaGetSymbolAddress((void**)&g, g_scratch);

    constexpr int SM128 = 3 * (128 + 128) * 36 * 4;   // 110,592 B
    constexpr int SM64  = 3 * (128 + 64)  * 36 * 4;   //  82,944 B
    static bool attr_done = false;
    if (!attr_done) {
        cudaFuncSetAttribute(gemm_nt<128>, cudaFuncAttributeMaxDynamicSharedMemorySize, SM128);
        cudaFuncSetAttribute(gemm_nt<64>,  cudaFuncAttributeMaxDynamicSharedMemorySize, SM64);
        attr_done = true;
    }

    dim3 tb(32, 8);

    // 0) weight transposes -> k-contiguous B operands
    transpose_k<<<dim3(96, 32), tb>>>(Wqkv, g + OFF_WQKVT, 1024, 3072);
    transpose_k<<<dim3(32, 32), tb>>>(Wr,   g + OFF_WRT,   1024, 1024);
    transpose_k<<<dim3(32, 32), tb>>>(Wo,   g + OFF_WOT,   1024, 1024);

    // 1) QKV projection (cat=[mems;w] via dual A pointer)
    gemm_nt<128><<<dim3(24, 32, 1), 256, SM128>>>(
        mems, w, 2048, 1024, 0, 0,
        g + OFF_WQKVT, 1024, 0, 0,
        g + OFF_QKV, 3072, 0, 0, 1024, 0);

    // 2) R projection
    gemm_nt<128><<<dim3(8, 16, 1), 256, SM128>>>(
        r, nullptr, 0, 1024, 0, 0,
        g + OFF_WRT, 1024, 0, 0,
        g + OFF_RK, 1024, 0, 0, 1024, 0);

    // 3) rank-1 bias terms (needs K and RK)
    bias_dot<<<dim3(8192, 2), 256>>>(rwb, rrb);

    // 4) AC = Q @ K^T  (z = n*2 + b; masked-tile skip)
    gemm_nt<128><<<dim3(16, 8, 32), 256, SM128>>>(
        g + OFF_QKV + 2048LL * 3072, nullptr, 0, 6144, 3072, 64,
        g + OFF_QKV + 1024,                      6144, 3072, 64,
        g + OFF_S, 2048, 2097152LL, 4194304LL, 64, 1);

    // 5) BD_pre = Q @ RK^T  (unused-tile skip)
    gemm_nt<128><<<dim3(16, 8, 32), 256, SM128>>>(
        g + OFF_QKV + 2048LL * 3072, nullptr, 0, 6144, 3072, 64,
        g + OFF_RK,                              1024, 0,    64,
        g + OFF_BD, 2048, 2097152LL, 4194304LL, 64, 2);

    // 6) shift + bias + mask + softmax (in place in S)
    softmax_kernel<<<dim3(1024, 32), 256>>>();

    // 7) V transpose to k-contiguous [z][64][2048]
    vtrans_kernel<<<dim3(64, 2, 32), tb>>>(g + OFF_QKV, g + OFF_VT);

    // 8) attn_vec = P @ V
    gemm_nt<64><<<dim3(1, 8, 32), 256, SM64>>>(
        g + OFF_S, nullptr, 0, 2048, 2097152LL, 4194304LL,
        g + OFF_VT, 2048, 131072LL, 262144LL,
        g + OFF_AV, 2048, 1024LL, 64LL, 2048, 0);

    // 9) output projection
    gemm_nt<128><<<dim3(8, 16, 1), 256, SM128>>>(
        g + OFF_AV, nullptr, 0, 1024, 0, 0,
        g + OFF_WOT, 1024, 0, 0,
        g + OFF_AO, 1024, 0, 0, 1024, 0);

    // 10) residual + LayerNorm
    ln_kernel<<<2048, 256>>>(w, gamma, beta, out);
}

// round 5
// speedup vs baseline: 6.1180x; 1.0317x over previous
#include <cuda_runtime.h>
#include <cstdint>
#include <math.h>

#define QLEN   1024
#define MEMLEN 1024
#define KLEN   2048
#define DM     1024

// ======================= scratch ============================================
static constexpr long long OFF_QKV   = 0;                            // [4096][3072]
static constexpr long long OFF_RK    = 12582912LL;                   // [2048][1024]
static constexpr long long OFF_S     = OFF_RK    + 2097152LL;        // [32][1024][2048]
static constexpr long long OFF_BD    = OFF_S     + 67108864LL;       // [32][1024][2048]
static constexpr long long OFF_AV    = OFF_BD    + 67108864LL;       // [2048][1024]
static constexpr long long OFF_AO    = OFF_AV    + 2097152LL;        // [2048][1024]
static constexpr long long OFF_WQKVT = OFF_AO    + 2097152LL;        // [3072][1024]
static constexpr long long OFF_WRT   = OFF_WQKVT + 3145728LL;        // [1024][1024]
static constexpr long long OFF_WOT   = OFF_WRT   + 1048576LL;        // [1024][1024]
static constexpr long long OFF_VT    = OFF_WOT   + 1048576LL;        // [32][64][2048]
static constexpr long long OFF_ACB   = OFF_VT    + 4194304LL;        // [32][2048]
static constexpr long long OFF_BDB   = OFF_ACB   + 65536LL;          // [32][2048]
static constexpr long long SCRATCH_TOTAL = OFF_BDB + 65536LL;

__device__ float g_scratch[SCRATCH_TOTAL];

// ======================= helpers ============================================
__device__ __forceinline__ uint32_t smem_u32(const void* p) {
    uint32_t a;
    asm("{ .reg .u64 t; cvta.to.shared.u64 t, %1; cvt.u32.u64 %0, t; }" : "=r"(a) : "l"(p));
    return a;
}
__device__ __forceinline__ void cp16(uint32_t s, const void* g) {
    asm volatile("cp.async.cg.shared.global [%0], [%1], 16;" :: "r"(s), "l"(g));
}
__device__ __forceinline__ void cp_commit() {
    asm volatile("cp.async.commit_group;");
}
template<int N> __device__ __forceinline__ void cp_wait() {
    asm volatile("cp.async.wait_group %0;" :: "n"(N));
}
__device__ __forceinline__ void mma_tf32(float* c, const uint32_t* a, const uint32_t* b)
{
    asm volatile(
        "mma.sync.aligned.m16n8k8.row.col.f32.tf32.tf32.f32 "
        "{%0,%1,%2,%3}, {%4,%5,%6,%7}, {%8,%9}, {%0,%1,%2,%3};"
        : "+f"(c[0]), "+f"(c[1]), "+f"(c[2]), "+f"(c[3])
        : "r"(a[0]), "r"(a[1]), "r"(a[2]), "r"(a[3]), "r"(b[0]), "r"(b[1]));
}
__device__ __forceinline__ void ldsm_x4(uint32_t* r, uint32_t addr) {
    asm volatile("ldmatrix.sync.aligned.m8n8.x4.shared.b16 {%0,%1,%2,%3}, [%4];"
        : "=r"(r[0]), "=r"(r[1]), "=r"(r[2]), "=r"(r[3]) : "r"(addr));
}
__device__ __forceinline__ void ldsm_x2(uint32_t* r, uint32_t addr) {
    asm volatile("ldmatrix.sync.aligned.m8n8.x2.shared.b16 {%0,%1}, [%2];"
        : "=r"(r[0]), "=r"(r[1]) : "r"(addr));
}

// ======================= pipelined NT GEMM (cp.async + ldmatrix + mma) ======
// C[M,N] = A[M,K] @ B[N,K]^T ; both operands k-contiguous in gmem.
// A dual-pointer handles the [mems; w] concat. Batched over blockIdx.z (z=n*2+b).
// skipmode: 0 none; 1 skip fully-masked AC tiles; 2 skip never-read BD_pre tiles;
//           3 cap K at row0+1152 (P @ V — probs are zero beyond the causal band).
template<int BN>
__global__ void __launch_bounds__(256, 2) gemm_nt(
    const float* __restrict__ A, const float* __restrict__ A2, int split, int lda,
    long long sAb, long long sAn,
    const float* __restrict__ B, int ldb, long long sBb, long long sBn,
    float* __restrict__ C, int ldc, long long sCb, long long sCn,
    int K, int skipmode)
{
    constexpr int BM = 128, LDSW = 36;
    constexpr int STAGE_A = BM * LDSW;           // floats
    constexpr int STAGE_B = BN * LDSW;
    constexpr int STAGE   = STAGE_A + STAGE_B;
    constexpr int ACH = BM * 32 / (4 * 256);     // 4 float4 chunks / thread
    constexpr int BCH = BN * 32 / (4 * 256);     // 4 or 2
    constexpr int WCOLS = (BN == 128) ? 4 : 2;
    constexpr int WROWS = 8 / WCOLS;
    constexpr int WM = BM / WROWS, WN = BN / WCOLS;
    constexpr int MT = WM / 16, NT = WN / 8;

    const int row0 = blockIdx.y * BM;
    const int col0 = blockIdx.x * BN;
    if (skipmode == 1 && col0 > row0 + (BM - 1) + MEMLEN) return;
    if (skipmode == 2 && col0 + BN - 1 < (QLEN - 1) - (row0 + BM - 1)) return;
    if (skipmode == 3) { const int klim = row0 + BM + MEMLEN; if (klim < K) K = klim; }

    extern __shared__ float smf[];
    const int tid = threadIdx.x, wid = tid >> 5, lane = tid & 31;
    const int grp = lane >> 2, tig = lane & 3;
    const int wr = wid / WCOLS, wc = wid % WCOLS;
    const int wm0 = wr * WM, wn0 = wc * WN;

    const int zb = blockIdx.z & 1, zn = blockIdx.z >> 1;
    A += (long long)zb * sAb + (long long)zn * sAn;
    if (A2) A2 += (long long)zb * sAb + (long long)zn * sAn;
    B += (long long)zb * sBb + (long long)zn * sBn;
    C += (long long)zb * sCb + (long long)zn * sCn;

    // staging map: element e = i*256+tid -> row lr+i*32, float4 col lc4
    const int lr = tid >> 3, lc4 = tid & 7;
    const float* aptr[ACH];
    #pragma unroll
    for (int i = 0; i < ACH; i++) {
        const int grow = row0 + lr + i * 32;
        const float* base = (A2 && grow >= split)
                            ? (A2 + (long long)(grow - split) * lda)
                            : (A  + (long long)grow * lda);
        aptr[i] = base + lc4 * 4;
    }
    const float* bptr[BCH];
    #pragma unroll
    for (int i = 0; i < BCH; i++)
        bptr[i] = B + (long long)(col0 + lr + i * 32) * ldb + lc4 * 4;

    const uint32_t s0   = smem_u32(smf);
    const uint32_t adst = (uint32_t)(lr * LDSW * 4 + lc4 * 16);
    const uint32_t bdst = (uint32_t)(STAGE_A * 4 + lr * LDSW * 4 + lc4 * 16);

    auto issue = [&](int s, int kb) {
        const uint32_t base = s0 + (uint32_t)s * (STAGE * 4);
        #pragma unroll
        for (int i = 0; i < ACH; i++)
            cp16(base + adst + (uint32_t)(i * 32 * LDSW * 4), aptr[i] + kb);
        #pragma unroll
        for (int i = 0; i < BCH; i++)
            cp16(base + bdst + (uint32_t)(i * 32 * LDSW * 4), bptr[i] + kb);
        cp_commit();
    };

    // ldmatrix per-lane source addressing
    // A x4: lanes 0-7 rows r+0..7 @k, 8-15 rows r+8..15 @k, 16-23 rows r+0..7 @k+4, 24-31 rows r+8..15 @k+4
    const int a_row = (lane & 7) + ((lane >> 3) & 1) * 8;
    const int a_c4  = (lane >> 4) * 4;
    // B x2: lanes 0-7 rows n+0..7 @k, 8-15 rows n+0..7 @k+4 (16-31 replicate)
    const int b_row = lane & 7;
    const int b_c4  = (((lane & 15) >> 3) & 1) * 4;

    const uint32_t a_lane_off = (uint32_t)(((wm0 + a_row) * LDSW + a_c4) * 4);
    const uint32_t b_lane_off = (uint32_t)((STAGE_A + (wn0 + b_row) * LDSW + b_c4) * 4);

    float acc[MT][NT][4];
    #pragma unroll
    for (int m = 0; m < MT; m++)
        #pragma unroll
        for (int n = 0; n < NT; n++)
            #pragma unroll
            for (int q = 0; q < 4; q++) acc[m][n][q] = 0.0f;

    const int T = K >> 5;
    issue(0, 0);
    if (T > 1) issue(1, 32); else cp_commit();

    int st = 0;
    for (int t = 0; t < T; t++) {
        cp_wait<1>();
        __syncthreads();

        const uint32_t sbase = s0 + (uint32_t)st * (STAGE * 4);
        const uint32_t abase = sbase + a_lane_off;
        const uint32_t bbase = sbase + b_lane_off;

        #pragma unroll
        for (int ks = 0; ks < 4; ks++) {
            uint32_t af[MT][4], bf[NT][2];
            #pragma unroll
            for (int m = 0; m < MT; m++)
                ldsm_x4(af[m], abase + (uint32_t)((m * 16 * LDSW + ks * 8) * 4));
            #pragma unroll
            for (int n = 0; n < NT; n++)
                ldsm_x2(bf[n], bbase + (uint32_t)((n * 8 * LDSW + ks * 8) * 4));
            #pragma unroll
            for (int m = 0; m < MT; m++)
                #pragma unroll
                for (int n = 0; n < NT; n++)
                    mma_tf32(acc[m][n], af[m], bf[n]);
        }

        const int tn = t + 2;
        if (tn < T) issue(tn % 3, tn * 32); else cp_commit();
        st++; if (st == 3) st = 0;
    }

    #pragma unroll
    for (int m = 0; m < MT; m++) {
        const int r = row0 + wm0 + m * 16 + grp;
        #pragma unroll
        for (int n = 0; n < NT; n++) {
            const int c = col0 + wn0 + n * 8 + 2 * tig;
            *(float2*)(C + (long long)r * ldc + c)       = make_float2(acc[m][n][0], acc[m][n][1]);
            *(float2*)(C + (long long)(r + 8) * ldc + c) = make_float2(acc[m][n][2], acc[m][n][3]);
        }
    }
}

// ======================= transposes =========================================
__global__ void transpose_k(const float* __restrict__ src, float* __restrict__ dst,
                            int rows, int cols)
{
    __shared__ float t[32][33];
    const int c0 = blockIdx.x * 32, r0 = blockIdx.y * 32;
    for (int i = threadIdx.y; i < 32; i += 8)
        t[i][threadIdx.x] = src[(long long)(r0 + i) * cols + c0 + threadIdx.x];
    __syncthreads();
    for (int i = threadIdx.y; i < 32; i += 8)
        dst[(long long)(c0 + i) * rows + r0 + threadIdx.x] = t[threadIdx.x][i];
}

// VT[z][d][j] = qkv[(j*2+zb)*3072 + 2048 + zn*64 + d],  z = zn*2+zb
__global__ void vtrans_kernel(const float* __restrict__ qkv, float* __restrict__ vt)
{
    __shared__ float t[32][33];
    const int j0 = blockIdx.x * 32;
    const int d0 = blockIdx.y * 32;
    const int z  = blockIdx.z;
    const int zb = z & 1, zn = z >> 1;
    for (int i = threadIdx.y; i < 32; i += 8)
        t[i][threadIdx.x] =
            qkv[(long long)((j0 + i) * 2 + zb) * 3072 + 2048 + zn * 64 + d0 + threadIdx.x];
    __syncthreads();
    float* dst = vt + (long long)z * 64 * 2048;
    for (int i = threadIdx.y; i < 32; i += 8)
        dst[(long long)(d0 + i) * 2048 + j0 + threadIdx.x] = t[threadIdx.x][i];
}

// ======================= rank-1 bias dots ===================================
// acb[z][j] = rwb[zn] . K[z][j]    (kind 0)
// bdb[z][p] = rrb[zn] . RK[p][zn]  (kind 1)
__global__ void bias_dot(const float* __restrict__ rwb, const float* __restrict__ rrb)
{
    const int gw   = blockIdx.x * 8 + (threadIdx.x >> 5);
    const int lane = threadIdx.x & 31;
    const int kind = blockIdx.y;
    const int z = gw >> 11, j = gw & 2047;
    const int zb = z & 1, zn = z >> 1;
    const float* bias = (kind ? rrb : rwb) + zn * 64;
    const float* row = kind
        ? g_scratch + OFF_RK  + (long long)j * 1024 + zn * 64
        : g_scratch + OFF_QKV + 1024 + (long long)(j * 2 + zb) * 3072 + zn * 64;
    float s = row[lane] * bias[lane] + row[lane + 32] * bias[lane + 32];
    #pragma unroll
    for (int o = 16; o; o >>= 1) s += __shfl_xor_sync(0xffffffffu, s, o);
    if (lane == 0)
        g_scratch[(kind ? OFF_BDB : OFF_ACB) + (long long)z * 2048 + j] = s;
}

// ======================= shift + bias + mask + softmax ======================
__global__ void __launch_bounds__(256) softmax_kernel()
{
    const int i = blockIdx.x;
    const int z = blockIdx.y;
    float*       srow = g_scratch + OFF_S  + (long long)z * QLEN * KLEN + (long long)i * KLEN;
    const float* brow = g_scratch + OFF_BD + (long long)z * QLEN * KLEN + (long long)i * KLEN;
    const float* acb  = g_scratch + OFF_ACB + (long long)z * 2048;
    const float* bdb  = g_scratch + OFF_BDB + (long long)z * 2048;
    const int limit = i + MEMLEN;                      // inclusive valid bound
    const int jmax  = min((i & ~127) + 1152, KLEN);    // PV never reads beyond this
    const int tid = threadIdx.x;

    float v[8];
    float lmax = -1e30f;
    #pragma unroll
    for (int u = 0; u < 8; u++) {
        const int j = tid + u * 256;
        if (j <= limit) {
            const int p = j - i + (QLEN - 1);
            const float val = (srow[j] + acb[j] + brow[p] + bdb[p]) * 0.125f;
            v[u] = val;
            lmax = fmaxf(lmax, val);
        } else {
            v[u] = -3.0e38f;
        }
    }
    __shared__ float red[256];
    red[tid] = lmax; __syncthreads();
    for (int s = 128; s; s >>= 1) { if (tid < s) red[tid] = fmaxf(red[tid], red[tid + s]); __syncthreads(); }
    const float m = red[0];
    __syncthreads();

    float lsum = 0.0f;
    #pragma unroll
    for (int u = 0; u < 8; u++) {
        const float e = expf(v[u] - m);                // masked lanes -> exactly 0
        v[u] = e; lsum += e;
    }
    red[tid] = lsum; __syncthreads();
    for (int s = 128; s; s >>= 1) { if (tid < s) red[tid] += red[tid + s]; __syncthreads(); }
    const float inv = 1.0f / red[0];

    #pragma unroll
    for (int u = 0; u < 8; u++) {
        const int j = tid + u * 256;
        if (j < jmax) srow[j] = v[u] * inv;
    }
}

// ======================= residual + LayerNorm ===============================
__global__ void __launch_bounds__(256) ln_kernel(
    const float* __restrict__ w,
    const float* __restrict__ gamma,
    const float* __restrict__ beta,
    float* __restrict__ out)
{
    const int row = blockIdx.x;
    const float* wr = w + (long long)row * DM;
    const float* ar = g_scratch + OFF_AO + (long long)row * DM;
    const int tid = threadIdx.x;

    float y[4];
    float s = 0.0f, s2 = 0.0f;
    #pragma unroll
    for (int u = 0; u < 4; u++) {
        const int c = tid + u * 256;
        y[u] = wr[c] + ar[c];
        s += y[u]; s2 += y[u] * y[u];
    }
    __shared__ float rs[256], rs2[256];
    rs[tid] = s; rs2[tid] = s2; __syncthreads();
    for (int st = 128; st; st >>= 1) {
        if (tid < st) { rs[tid] += rs[tid + st]; rs2[tid] += rs2[tid + st]; }
        __syncthreads();
    }
    const float mu   = rs[0]  * (1.0f / 1024.0f);
    const float var  = rs2[0] * (1.0f / 1024.0f) - mu * mu;
    const float rstd = rsqrtf(var + 1e-5f);
    #pragma unroll
    for (int u = 0; u < 4; u++) {
        const int c = tid + u * 256;
        out[(long long)row * DM + c] = (y[u] - mu) * rstd * gamma[c] + beta[c];
    }
}

// ======================= launch =============================================
extern "C" void kernel_launch(void* const* d_in, const int* in_sizes, int n_in,
                              void* d_out, int out_size)
{
    (void)in_sizes; (void)n_in; (void)out_size;
    const float* w     = (const float*)d_in[0];   // [1024,2,1024]
    const float* r     = (const float*)d_in[1];   // [2048,1024]
    const float* rwb   = (const float*)d_in[2];   // [16,64]
    const float* rrb   = (const float*)d_in[3];   // [16,64]
    const float* mems  = (const float*)d_in[4];   // [1024,2,1024]
    /* d_in[5] = attn_mask (deterministic, unused) */
    const float* Wqkv  = (const float*)d_in[6];   // [1024,3072]
    const float* Wr    = (const float*)d_in[7];   // [1024,1024]
    const float* Wo    = (const float*)d_in[8];   // [1024,1024]
    const float* gamma = (const float*)d_in[9];
    const float* beta  = (const float*)d_in[10];
    float* out = (float*)d_out;

    float* g = nullptr;
    cudaGetSymbolAddress((void**)&g, g_scratch);

    constexpr int SM128 = 3 * (128 + 128) * 36 * 4;   // 110,592 B
    constexpr int SM64  = 3 * (128 + 64)  * 36 * 4;   //  82,944 B
    static bool attr_done = false;
    if (!attr_done) {
        cudaFuncSetAttribute(gemm_nt<128>, cudaFuncAttributeMaxDynamicSharedMemorySize, SM128);
        cudaFuncSetAttribute(gemm_nt<64>,  cudaFuncAttributeMaxDynamicSharedMemorySize, SM64);
        attr_done = true;
    }

    dim3 tb(32, 8);

    // 0) weight transposes -> k-contiguous B operands
    transpose_k<<<dim3(96, 32), tb>>>(Wqkv, g + OFF_WQKVT, 1024, 3072);
    transpose_k<<<dim3(32, 32), tb>>>(Wr,   g + OFF_WRT,   1024, 1024);
    transpose_k<<<dim3(32, 32), tb>>>(Wo,   g + OFF_WOT,   1024, 1024);

    // 1) QKV projection (cat=[mems;w] via dual A pointer)
    gemm_nt<128><<<dim3(24, 32, 1), 256, SM128>>>(
        mems, w, 2048, 1024, 0, 0,
        g + OFF_WQKVT, 1024, 0, 0,
        g + OFF_QKV, 3072, 0, 0, 1024, 0);

    // 2) R projection
    gemm_nt<128><<<dim3(8, 16, 1), 256, SM128>>>(
        r, nullptr, 0, 1024, 0, 0,
        g + OFF_WRT, 1024, 0, 0,
        g + OFF_RK, 1024, 0, 0, 1024, 0);

    // 3) rank-1 bias terms (needs K and RK)
    bias_dot<<<dim3(8192, 2), 256>>>(rwb, rrb);

    // 4) AC = Q @ K^T  (z = n*2 + b; masked-tile skip)
    gemm_nt<128><<<dim3(16, 8, 32), 256, SM128>>>(
        g + OFF_QKV + 2048LL * 3072, nullptr, 0, 6144, 3072, 64,
        g + OFF_QKV + 1024,                      6144, 3072, 64,
        g + OFF_S, 2048, 2097152LL, 4194304LL, 64, 1);

    // 5) BD_pre = Q @ RK^T  (unused-tile skip)
    gemm_nt<128><<<dim3(16, 8, 32), 256, SM128>>>(
        g + OFF_QKV + 2048LL * 3072, nullptr, 0, 6144, 3072, 64,
        g + OFF_RK,                              1024, 0,    64,
        g + OFF_BD, 2048, 2097152LL, 4194304LL, 64, 2);

    // 6) shift + bias + mask + softmax (in place in S)
    softmax_kernel<<<dim3(1024, 32), 256>>>();

    // 7) V transpose to k-contiguous [z][64][2048]
    vtrans_kernel<<<dim3(64, 2, 32), tb>>>(g + OFF_QKV, g + OFF_VT);

    // 8) attn_vec = P @ V  (K capped per M-block via skipmode 3)
    gemm_nt<64><<<dim3(1, 8, 32), 256, SM64>>>(
        g + OFF_S, nullptr, 0, 2048, 2097152LL, 4194304LL,
        g + OFF_VT, 2048, 131072LL, 262144LL,
        g + OFF_AV, 2048, 1024LL, 64LL, 2048, 3);

    // 9) output projection
    gemm_nt<128><<<dim3(8, 16, 1), 256, SM128>>>(
        g + OFF_AV, nullptr, 0, 1024, 0, 0,
        g + OFF_WOT, 1024, 0, 0,
        g + OFF_AO, 1024, 0, 0, 1024, 0);

    // 10) residual + LayerNorm
    ln_kernel<<<2048, 256>>>(w, gamma, beta, out);
}

// round 6
// speedup vs baseline: 8.3448x; 1.3640x over previous
#include <cuda_runtime.h>
#include <cuda_fp16.h>
#include <cstdint>
#include <math.h>

#define QLEN   1024
#define MEMLEN 1024
#define KLEN   2048
#define DM     1024

// ======================= scratch (units: floats) ============================
static constexpr long long OFF_QKV16 = 0;                            // half [4096][3072]
static constexpr long long OFF_RK16  = OFF_QKV16 + 6291456LL;        // half [2048][1024]
static constexpr long long OFF_CAT16 = OFF_RK16  + 1048576LL;        // half [4096][1024]
static constexpr long long OFF_R16   = OFF_CAT16 + 2097152LL;        // half [2048][1024]
static constexpr long long OFF_S     = OFF_R16   + 1048576LL;        // f32  [32][1024][2048]
static constexpr long long OFF_BD    = OFF_S     + 67108864LL;       // f32  [32][1024][2048]
static constexpr long long OFF_P16   = OFF_BD    + 67108864LL;       // half [32][1024][2048]
static constexpr long long OFF_AV16  = OFF_P16   + 33554432LL;       // half [2048][1024]
static constexpr long long OFF_AO    = OFF_AV16  + 1048576LL;        // f32  [2048][1024]
static constexpr long long OFF_WQKVT = OFF_AO    + 2097152LL;        // half [3072][1024]
static constexpr long long OFF_WRT   = OFF_WQKVT + 1572864LL;        // half [1024][1024]
static constexpr long long OFF_WOT   = OFF_WRT   + 524288LL;         // half [1024][1024]
static constexpr long long OFF_VT16  = OFF_WOT   + 524288LL;         // half [32][64][2048]
static constexpr long long OFF_ACB   = OFF_VT16  + 2097152LL;        // f32  [32][2048]
static constexpr long long OFF_BDB   = OFF_ACB   + 65536LL;          // f32  [32][2048]
static constexpr long long SCRATCH_TOTAL = OFF_BDB + 65536LL;

__device__ float g_scratch[SCRATCH_TOTAL];

// ======================= helpers ============================================
__device__ __forceinline__ uint32_t smem_u32(const void* p) {
    uint32_t a;
    asm("{ .reg .u64 t; cvta.to.shared.u64 t, %1; cvt.u32.u64 %0, t; }" : "=r"(a) : "l"(p));
    return a;
}
__device__ __forceinline__ void cp16(uint32_t s, const void* g) {
    asm volatile("cp.async.cg.shared.global [%0], [%1], 16;" :: "r"(s), "l"(g));
}
__device__ __forceinline__ void cp_commit() {
    asm volatile("cp.async.commit_group;");
}
template<int N> __device__ __forceinline__ void cp_wait() {
    asm volatile("cp.async.wait_group %0;" :: "n"(N));
}
__device__ __forceinline__ void mma_f16(float* c, const uint32_t* a, const uint32_t* b)
{
    asm volatile(
        "mma.sync.aligned.m16n8k16.row.col.f32.f16.f16.f32 "
        "{%0,%1,%2,%3}, {%4,%5,%6,%7}, {%8,%9}, {%0,%1,%2,%3};"
        : "+f"(c[0]), "+f"(c[1]), "+f"(c[2]), "+f"(c[3])
        : "r"(a[0]), "r"(a[1]), "r"(a[2]), "r"(a[3]), "r"(b[0]), "r"(b[1]));
}
__device__ __forceinline__ void ldsm_x4(uint32_t* r, uint32_t addr) {
    asm volatile("ldmatrix.sync.aligned.m8n8.x4.shared.b16 {%0,%1,%2,%3}, [%4];"
        : "=r"(r[0]), "=r"(r[1]), "=r"(r[2]), "=r"(r[3]) : "r"(addr));
}
__device__ __forceinline__ void ldsm_x2(uint32_t* r, uint32_t addr) {
    asm volatile("ldmatrix.sync.aligned.m8n8.x2.shared.b16 {%0,%1}, [%2];"
        : "=r"(r[0]), "=r"(r[1]) : "r"(addr));
}

// ======================= pipelined fp16 NT GEMM =============================
// C[M,N] = A[M,K] @ B[N,K]^T ; fp16 operands k-contiguous in gmem, fp32 accum.
// TC = float or __half output. Batched over blockIdx.z (z = n*2 + b).
// skipmode: 0 none; 1 skip fully-masked AC tiles; 2 skip never-read BD_pre tiles;
//           3 cap K at row0+1152 (P @ V).
template<int BN, typename TC>
__global__ void __launch_bounds__(256, 2) gemm_h(
    const __half* __restrict__ A, int lda, long long sAb, long long sAn,
    const __half* __restrict__ B, int ldb, long long sBb, long long sBn,
    TC* __restrict__ C, int ldc, long long sCb, long long sCn,
    int K, int skipmode)
{
    constexpr int BM = 128, BK = 64, LDSW = 72;       // halves; 144B row stride
    constexpr int STAGE_A = BM * LDSW;                // halves
    constexpr int STAGE_B = BN * LDSW;
    constexpr uint32_t STAGE_BYTES = (STAGE_A + STAGE_B) * 2;
    constexpr int ACH = BM / 32;                      // 4 cp16 / thread for A
    constexpr int BCH = BN / 32;                      // 4 or 2
    constexpr int WCOLS = (BN == 128) ? 4 : 2;
    constexpr int WROWS = 8 / WCOLS;
    constexpr int WM = BM / WROWS, WN = BN / WCOLS;
    constexpr int MT = WM / 16, NT = WN / 8;

    const int row0 = blockIdx.y * BM;
    const int col0 = blockIdx.x * BN;
    if (skipmode == 1 && col0 > row0 + (BM - 1) + MEMLEN) return;
    if (skipmode == 2 && col0 + BN - 1 < (QLEN - 1) - (row0 + BM - 1)) return;
    if (skipmode == 3) { const int klim = row0 + BM + MEMLEN; if (klim < K) K = klim; }

    extern __shared__ __half smh[];
    const int tid = threadIdx.x, wid = tid >> 5, lane = tid & 31;
    const int grp = lane >> 2, tig = lane & 3;
    const int wr = wid / WCOLS, wc = wid % WCOLS;
    const int wm0 = wr * WM, wn0 = wc * WN;

    const int zb = blockIdx.z & 1, zn = blockIdx.z >> 1;
    A += (long long)zb * sAb + (long long)zn * sAn;
    B += (long long)zb * sBb + (long long)zn * sBn;
    C += (long long)zb * sCb + (long long)zn * sCn;

    // staging: thread -> row lr (32 rows/iter), 16B chunk lc4 (8 chunks = 64 halves)
    const int lr = tid >> 3, lc4 = tid & 7;
    const __half* aptr[ACH];
    #pragma unroll
    for (int i = 0; i < ACH; i++)
        aptr[i] = A + (long long)(row0 + lr + i * 32) * lda + lc4 * 8;
    const __half* bptr[BCH];
    #pragma unroll
    for (int i = 0; i < BCH; i++)
        bptr[i] = B + (long long)(col0 + lr + i * 32) * ldb + lc4 * 8;

    const uint32_t s0   = smem_u32(smh);
    const uint32_t adst = (uint32_t)((lr * LDSW + lc4 * 8) * 2);
    const uint32_t bdst = (uint32_t)((STAGE_A + lr * LDSW + lc4 * 8) * 2);

    auto issue = [&](int s, int kb) {
        const uint32_t base = s0 + (uint32_t)s * STAGE_BYTES;
        #pragma unroll
        for (int i = 0; i < ACH; i++)
            cp16(base + adst + (uint32_t)(i * 32 * LDSW * 2), aptr[i] + kb);
        #pragma unroll
        for (int i = 0; i < BCH; i++)
            cp16(base + bdst + (uint32_t)(i * 32 * LDSW * 2), bptr[i] + kb);
        cp_commit();
    };

    // ldmatrix lane addressing (canonical m16n8k16)
    const uint32_t a_lane_off =
        (uint32_t)(((wm0 + (lane & 15)) * LDSW + (lane >> 4) * 8) * 2);
    const uint32_t b_lane_off =
        (uint32_t)((STAGE_A + (wn0 + (lane & 7)) * LDSW + ((lane >> 3) & 1) * 8) * 2);

    float acc[MT][NT][4];
    #pragma unroll
    for (int m = 0; m < MT; m++)
        #pragma unroll
        for (int n = 0; n < NT; n++)
            #pragma unroll
            for (int q = 0; q < 4; q++) acc[m][n][q] = 0.0f;

    const int T = K >> 6;
    issue(0, 0);
    if (T > 1) issue(1, 64); else cp_commit();

    int st = 0;
    for (int t = 0; t < T; t++) {
        cp_wait<1>();
        __syncthreads();

        const uint32_t sbase = s0 + (uint32_t)st * STAGE_BYTES;
        const uint32_t abase = sbase + a_lane_off;
        const uint32_t bbase = sbase + b_lane_off;

        #pragma unroll
        for (int ks = 0; ks < 4; ks++) {           // 4 x k16 per 64-k tile
            uint32_t af[MT][4], bf[NT][2];
            #pragma unroll
            for (int m = 0; m < MT; m++)
                ldsm_x4(af[m], abase + (uint32_t)((m * 16 * LDSW + ks * 16) * 2));
            #pragma unroll
            for (int n = 0; n < NT; n++)
                ldsm_x2(bf[n], bbase + (uint32_t)((n * 8 * LDSW + ks * 16) * 2));
            #pragma unroll
            for (int m = 0; m < MT; m++)
                #pragma unroll
                for (int n = 0; n < NT; n++)
                    mma_f16(acc[m][n], af[m], bf[n]);
        }

        const int tn = t + 2;
        if (tn < T) issue(tn % 3, tn * 64); else cp_commit();
        st++; if (st == 3) st = 0;
    }

    #pragma unroll
    for (int m = 0; m < MT; m++) {
        const int r = row0 + wm0 + m * 16 + grp;
        #pragma unroll
        for (int n = 0; n < NT; n++) {
            const int c = col0 + wn0 + n * 8 + 2 * tig;
            if constexpr (sizeof(TC) == 4) {
                *(float2*)((float*)C + (long long)r * ldc + c)
                    = make_float2(acc[m][n][0], acc[m][n][1]);
                *(float2*)((float*)C + (long long)(r + 8) * ldc + c)
                    = make_float2(acc[m][n][2], acc[m][n][3]);
            } else {
                *(__half2*)((__half*)C + (long long)r * ldc + c)
                    = __floats2half2_rn(acc[m][n][0], acc[m][n][1]);
                *(__half2*)((__half*)C + (long long)(r + 8) * ldc + c)
                    = __floats2half2_rn(acc[m][n][2], acc[m][n][3]);
            }
        }
    }
}

// ======================= fp32 -> fp16 converts ==============================
__global__ void cvt_cat(const float* __restrict__ mems, const float* __restrict__ w,
                        __half* __restrict__ dst)
{
    const int i = blockIdx.x * 256 + threadIdx.x;          // float4 index, 1M total
    const float4 v = (i < 524288) ? ((const float4*)mems)[i]
                                  : ((const float4*)w)[i - 524288];
    ((__half2*)dst)[2 * i]     = __floats2half2_rn(v.x, v.y);
    ((__half2*)dst)[2 * i + 1] = __floats2half2_rn(v.z, v.w);
}
__global__ void cvt_h(const float* __restrict__ src, __half* __restrict__ dst)
{
    const int i = blockIdx.x * 256 + threadIdx.x;
    const float4 v = ((const float4*)src)[i];
    ((__half2*)dst)[2 * i]     = __floats2half2_rn(v.x, v.y);
    ((__half2*)dst)[2 * i + 1] = __floats2half2_rn(v.z, v.w);
}

// ======================= transposes (fp32 in -> fp16 out) ===================
__global__ void transpose_kh(const float* __restrict__ src, __half* __restrict__ dst,
                             int rows, int cols)
{
    __shared__ float t[32][33];
    const int c0 = blockIdx.x * 32, r0 = blockIdx.y * 32;
    for (int i = threadIdx.y; i < 32; i += 8)
        t[i][threadIdx.x] = src[(long long)(r0 + i) * cols + c0 + threadIdx.x];
    __syncthreads();
    for (int i = threadIdx.y; i < 32; i += 8)
        dst[(long long)(c0 + i) * rows + r0 + threadIdx.x] = __float2half_rn(t[threadIdx.x][i]);
}

// VT16[z][d][j] = qkv16[(j*2+zb)*3072 + 2048 + zn*64 + d]
__global__ void vtrans_h(const __half* __restrict__ qkv, __half* __restrict__ vt)
{
    __shared__ __half t[32][34];
    const int j0 = blockIdx.x * 32;
    const int d0 = blockIdx.y * 32;
    const int z  = blockIdx.z;
    const int zb = z & 1, zn = z >> 1;
    for (int i = threadIdx.y; i < 32; i += 8)
        t[i][threadIdx.x] =
            qkv[(long long)((j0 + i) * 2 + zb) * 3072 + 2048 + zn * 64 + d0 + threadIdx.x];
    __syncthreads();
    __half* dst = vt + (long long)z * 64 * 2048;
    for (int i = threadIdx.y; i < 32; i += 8)
        dst[(long long)(d0 + i) * 2048 + j0 + threadIdx.x] = t[threadIdx.x][i];
}

// ======================= rank-1 bias dots ===================================
__global__ void bias_dot(const float* __restrict__ rwb, const float* __restrict__ rrb)
{
    const int gw   = blockIdx.x * 8 + (threadIdx.x >> 5);
    const int lane = threadIdx.x & 31;
    const int kind = blockIdx.y;
    const int z = gw >> 11, j = gw & 2047;
    const int zb = z & 1, zn = z >> 1;
    const float* bias = (kind ? rrb : rwb) + zn * 64;
    const __half* row = kind
        ? (const __half*)(g_scratch + OFF_RK16)  + (long long)j * 1024 + zn * 64
        : (const __half*)(g_scratch + OFF_QKV16) + (long long)(j * 2 + zb) * 3072 + 1024 + zn * 64;
    float s = __half2float(row[lane]) * bias[lane]
            + __half2float(row[lane + 32]) * bias[lane + 32];
    #pragma unroll
    for (int o = 16; o; o >>= 1) s += __shfl_xor_sync(0xffffffffu, s, o);
    if (lane == 0)
        g_scratch[(kind ? OFF_BDB : OFF_ACB) + (long long)z * 2048 + j] = s;
}

// ======================= shift + bias + mask + softmax ======================
// reads fp32 AC/BD + rank-1 terms; writes fp16 probs into P16
__global__ void __launch_bounds__(256) softmax_kernel()
{
    const int i = blockIdx.x;
    const int z = blockIdx.y;
    const float* srow = g_scratch + OFF_S  + (long long)z * QLEN * KLEN + (long long)i * KLEN;
    const float* brow = g_scratch + OFF_BD + (long long)z * QLEN * KLEN + (long long)i * KLEN;
    const float* acb  = g_scratch + OFF_ACB + (long long)z * 2048;
    const float* bdb  = g_scratch + OFF_BDB + (long long)z * 2048;
    __half* prow = (__half*)(g_scratch + OFF_P16) + (long long)z * QLEN * KLEN + (long long)i * KLEN;
    const int limit = i + MEMLEN;                      // inclusive valid bound
    const int jmax  = min((i & ~127) + 1152, KLEN);    // PV never reads beyond this
    const int tid = threadIdx.x;

    float v[8];
    float lmax = -1e30f;
    #pragma unroll
    for (int u = 0; u < 8; u++) {
        const int j = tid + u * 256;
        if (j <= limit) {
            const int p = j - i + (QLEN - 1);
            const float val = (srow[j] + acb[j] + brow[p] + bdb[p]) * 0.125f;
            v[u] = val;
            lmax = fmaxf(lmax, val);
        } else {
            v[u] = -3.0e38f;
        }
    }
    __shared__ float red[256];
    red[tid] = lmax; __syncthreads();
    for (int s = 128; s; s >>= 1) { if (tid < s) red[tid] = fmaxf(red[tid], red[tid + s]); __syncthreads(); }
    const float m = red[0];
    __syncthreads();

    float lsum = 0.0f;
    #pragma unroll
    for (int u = 0; u < 8; u++) {
        const float e = expf(v[u] - m);                // masked lanes -> exactly 0
        v[u] = e; lsum += e;
    }
    red[tid] = lsum; __syncthreads();
    for (int s = 128; s; s >>= 1) { if (tid < s) red[tid] += red[tid + s]; __syncthreads(); }
    const float inv = 1.0f / red[0];

    #pragma unroll
    for (int u = 0; u < 8; u++) {
        const int j = tid + u * 256;
        if (j < jmax) prow[j] = __float2half_rn(v[u] * inv);
    }
}

// ======================= residual + LayerNorm ===============================
__global__ void __launch_bounds__(256) ln_kernel(
    const float* __restrict__ w,
    const float* __restrict__ gamma,
    const float* __restrict__ beta,
    float* __restrict__ out)
{
    const int row = blockIdx.x;
    const float* wr = w + (long long)row * DM;
    const float* ar = g_scratch + OFF_AO + (long long)row * DM;
    const int tid = threadIdx.x;

    float y[4];
    float s = 0.0f, s2 = 0.0f;
    #pragma unroll
    for (int u = 0; u < 4; u++) {
        const int c = tid + u * 256;
        y[u] = wr[c] + ar[c];
        s += y[u]; s2 += y[u] * y[u];
    }
    __shared__ float rs[256], rs2[256];
    rs[tid] = s; rs2[tid] = s2; __syncthreads();
    for (int st = 128; st; st >>= 1) {
        if (tid < st) { rs[tid] += rs[tid + st]; rs2[tid] += rs2[tid + st]; }
        __syncthreads();
    }
    const float mu   = rs[0]  * (1.0f / 1024.0f);
    const float var  = rs2[0] * (1.0f / 1024.0f) - mu * mu;
    const float rstd = rsqrtf(var + 1e-5f);
    #pragma unroll
    for (int u = 0; u < 4; u++) {
        const int c = tid + u * 256;
        out[(long long)row * DM + c] = (y[u] - mu) * rstd * gamma[c] + beta[c];
    }
}

// ======================= launch =============================================
extern "C" void kernel_launch(void* const* d_in, const int* in_sizes, int n_in,
                              void* d_out, int out_size)
{
    (void)in_sizes; (void)n_in; (void)out_size;
    const float* w     = (const float*)d_in[0];   // [1024,2,1024]
    const float* r     = (const float*)d_in[1];   // [2048,1024]
    const float* rwb   = (const float*)d_in[2];   // [16,64]
    const float* rrb   = (const float*)d_in[3];   // [16,64]
    const float* mems  = (const float*)d_in[4];   // [1024,2,1024]
    /* d_in[5] = attn_mask (deterministic, unused) */
    const float* Wqkv  = (const float*)d_in[6];   // [1024,3072]
    const float* Wr    = (const float*)d_in[7];   // [1024,1024]
    const float* Wo    = (const float*)d_in[8];   // [1024,1024]
    const float* gamma = (const float*)d_in[9];
    const float* beta  = (const float*)d_in[10];
    float* out = (float*)d_out;

    float* g = nullptr;
    cudaGetSymbolAddress((void**)&g, g_scratch);
    __half* qkv16 = (__half*)(g + OFF_QKV16);
    __half* rk16  = (__half*)(g + OFF_RK16);
    __half* cat16 = (__half*)(g + OFF_CAT16);
    __half* r16   = (__half*)(g + OFF_R16);
    __half* p16   = (__half*)(g + OFF_P16);
    __half* av16  = (__half*)(g + OFF_AV16);
    __half* wqkvt = (__half*)(g + OFF_WQKVT);
    __half* wrt   = (__half*)(g + OFF_WRT);
    __half* wot   = (__half*)(g + OFF_WOT);
    __half* vt16  = (__half*)(g + OFF_VT16);

    constexpr int SM128 = 3 * (128 + 128) * 72 * 2;   // 110,592 B
    constexpr int SM64  = 3 * (128 + 64)  * 72 * 2;   //  82,944 B
    static bool attr_done = false;
    if (!attr_done) {
        cudaFuncSetAttribute((void*)gemm_h<128, float>,  cudaFuncAttributeMaxDynamicSharedMemorySize, SM128);
        cudaFuncSetAttribute((void*)gemm_h<128, __half>, cudaFuncAttributeMaxDynamicSharedMemorySize, SM128);
        cudaFuncSetAttribute((void*)gemm_h<64,  __half>, cudaFuncAttributeMaxDynamicSharedMemorySize, SM64);
        attr_done = true;
    }

    dim3 tb(32, 8);

    // 0) fp16 conversions + weight transposes
    cvt_cat<<<4096, 256>>>(mems, w, cat16);
    cvt_h<<<2048, 256>>>(r, r16);
    transpose_kh<<<dim3(96, 32), tb>>>(Wqkv, wqkvt, 1024, 3072);
    transpose_kh<<<dim3(32, 32), tb>>>(Wr,   wrt,   1024, 1024);
    transpose_kh<<<dim3(32, 32), tb>>>(Wo,   wot,   1024, 1024);

    // 1) QKV projection -> fp16
    gemm_h<128, __half><<<dim3(24, 32, 1), 256, SM128>>>(
        cat16, 1024, 0, 0,
        wqkvt, 1024, 0, 0,
        qkv16, 3072, 0, 0, 1024, 0);

    // 2) R projection -> fp16
    gemm_h<128, __half><<<dim3(8, 16, 1), 256, SM128>>>(
        r16, 1024, 0, 0,
        wrt, 1024, 0, 0,
        rk16, 1024, 0, 0, 1024, 0);

    // 3) rank-1 bias terms
    bias_dot<<<dim3(8192, 2), 256>>>(rwb, rrb);

    // 4) AC = Q @ K^T -> fp32  (z = n*2 + b; masked-tile skip)
    gemm_h<128, float><<<dim3(16, 8, 32), 256, SM128>>>(
        qkv16 + 2048LL * 3072, 6144, 3072, 64,
        qkv16 + 1024,          6144, 3072, 64,
        g + OFF_S, 2048, 2097152LL, 4194304LL, 64, 1);

    // 5) BD_pre = Q @ RK^T -> fp32  (unused-tile skip)
    gemm_h<128, float><<<dim3(16, 8, 32), 256, SM128>>>(
        qkv16 + 2048LL * 3072, 6144, 3072, 64,
        rk16,                  1024, 0,    64,
        g + OFF_BD, 2048, 2097152LL, 4194304LL, 64, 2);

    // 6) shift + bias + mask + softmax -> fp16 probs
    softmax_kernel<<<dim3(1024, 32), 256>>>();

    // 7) V transpose -> fp16 [z][64][2048]
    vtrans_h<<<dim3(64, 2, 32), tb>>>(qkv16, vt16);

    // 8) attn_vec = P @ V -> fp16 (K capped per M-block)
    gemm_h<64, __half><<<dim3(1, 8, 32), 256, SM64>>>(
        p16,  2048, 2097152LL, 4194304LL,
        vt16, 2048, 131072LL,  262144LL,
        av16, 2048, 1024LL, 64LL, 2048, 3);

    // 9) output projection -> fp32
    gemm_h<128, float><<<dim3(8, 16, 1), 256, SM128>>>(
        av16, 1024, 0, 0,
        wot,  1024, 0, 0,
        g + OFF_AO, 1024, 0, 0, 1024, 0);

    // 10) residual + LayerNorm
    ln_kernel<<<2048, 256>>>(w, gamma, beta, out);
}

// round 7
// speedup vs baseline: 8.6337x; 1.0346x over previous
#include <cuda_runtime.h>
#include <cuda_fp16.h>
#include <cstdint>
#include <math.h>

#define QLEN   1024
#define MEMLEN 1024
#define KLEN   2048
#define DM     1024

// ======================= scratch (units: floats) ============================
static constexpr long long OFF_QKV16 = 0;                            // half [4096][3072]
static constexpr long long OFF_RK16  = OFF_QKV16 + 6291456LL;        // half [2048][1024]
static constexpr long long OFF_CAT16 = OFF_RK16  + 1048576LL;        // half [4096][1024]
static constexpr long long OFF_R16   = OFF_CAT16 + 2097152LL;        // half [2048][1024]
static constexpr long long OFF_S16   = OFF_R16   + 1048576LL;        // half [32][1024][2048] scores -> probs (in place)
static constexpr long long OFF_BD16  = OFF_S16   + 33554432LL;       // half [32][1024][2048]
static constexpr long long OFF_AV16  = OFF_BD16  + 33554432LL;       // half [2048][1024]
static constexpr long long OFF_AO    = OFF_AV16  + 1048576LL;        // f32  [2048][1024]
static constexpr long long OFF_WQKVT = OFF_AO    + 2097152LL;        // half [3072][1024]
static constexpr long long OFF_WRT   = OFF_WQKVT + 1572864LL;        // half [1024][1024]
static constexpr long long OFF_WOT   = OFF_WRT   + 524288LL;         // half [1024][1024]
static constexpr long long OFF_VT16  = OFF_WOT   + 524288LL;         // half [32][64][2048]
static constexpr long long OFF_ACB   = OFF_VT16  + 2097152LL;        // f32  [32][2048]
static constexpr long long OFF_BDB   = OFF_ACB   + 65536LL;          // f32  [32][2048]
static constexpr long long SCRATCH_TOTAL = OFF_BDB + 65536LL;

__device__ float g_scratch[SCRATCH_TOTAL];

// ======================= helpers ============================================
__device__ __forceinline__ uint32_t smem_u32(const void* p) {
    uint32_t a;
    asm("{ .reg .u64 t; cvta.to.shared.u64 t, %1; cvt.u32.u64 %0, t; }" : "=r"(a) : "l"(p));
    return a;
}
__device__ __forceinline__ void cp16(uint32_t s, const void* g) {
    asm volatile("cp.async.cg.shared.global [%0], [%1], 16;" :: "r"(s), "l"(g));
}
__device__ __forceinline__ void cp_commit() {
    asm volatile("cp.async.commit_group;");
}
template<int N> __device__ __forceinline__ void cp_wait() {
    asm volatile("cp.async.wait_group %0;" :: "n"(N));
}
__device__ __forceinline__ void mma_f16(float* c, const uint32_t* a, const uint32_t* b)
{
    asm volatile(
        "mma.sync.aligned.m16n8k16.row.col.f32.f16.f16.f32 "
        "{%0,%1,%2,%3}, {%4,%5,%6,%7}, {%8,%9}, {%0,%1,%2,%3};"
        : "+f"(c[0]), "+f"(c[1]), "+f"(c[2]), "+f"(c[3])
        : "r"(a[0]), "r"(a[1]), "r"(a[2]), "r"(a[3]), "r"(b[0]), "r"(b[1]));
}
__device__ __forceinline__ void ldsm_x4(uint32_t* r, uint32_t addr) {
    asm volatile("ldmatrix.sync.aligned.m8n8.x4.shared.b16 {%0,%1,%2,%3}, [%4];"
        : "=r"(r[0]), "=r"(r[1]), "=r"(r[2]), "=r"(r[3]) : "r"(addr));
}
__device__ __forceinline__ void ldsm_x2(uint32_t* r, uint32_t addr) {
    asm volatile("ldmatrix.sync.aligned.m8n8.x2.shared.b16 {%0,%1}, [%2];"
        : "=r"(r[0]), "=r"(r[1]) : "r"(addr));
}

// ======================= pipelined fp16 NT GEMM =============================
// C[M,N] = A[M,K] @ B[N,K]^T ; fp16 operands k-contiguous in gmem, fp32 accum.
// TC = float or __half output. Batched over blockIdx.z (z = n*2 + b).
// skipmode: 0 none; 1 skip fully-masked AC tiles; 2 skip never-read BD_pre tiles;
//           3 cap K at row0+1152 (P @ V).
template<int BN, typename TC>
__global__ void __launch_bounds__(256, 2) gemm_h(
    const __half* __restrict__ A, int lda, long long sAb, long long sAn,
    const __half* __restrict__ B, int ldb, long long sBb, long long sBn,
    TC* __restrict__ C, int ldc, long long sCb, long long sCn,
    int K, int skipmode)
{
    constexpr int BM = 128, LDSW = 72;                // halves; 144B row stride
    constexpr int STAGE_A = BM * LDSW;                // halves
    constexpr int STAGE_B = BN * LDSW;
    constexpr uint32_t STAGE_BYTES = (STAGE_A + STAGE_B) * 2;
    constexpr int ACH = BM / 32;
    constexpr int BCH = BN / 32;
    constexpr int WCOLS = (BN == 128) ? 4 : 2;
    constexpr int WROWS = 8 / WCOLS;
    constexpr int WM = BM / WROWS, WN = BN / WCOLS;
    constexpr int MT = WM / 16, NT = WN / 8;

    const int row0 = blockIdx.y * BM;
    const int col0 = blockIdx.x * BN;
    if (skipmode == 1 && col0 > row0 + (BM - 1) + MEMLEN) return;
    if (skipmode == 2 && col0 + BN - 1 < (QLEN - 1) - (row0 + BM - 1)) return;
    if (skipmode == 3) { const int klim = row0 + BM + MEMLEN; if (klim < K) K = klim; }

    extern __shared__ __half smh[];
    const int tid = threadIdx.x, wid = tid >> 5, lane = tid & 31;
    const int grp = lane >> 2, tig = lane & 3;
    const int wr = wid / WCOLS, wc = wid % WCOLS;
    const int wm0 = wr * WM, wn0 = wc * WN;

    const int zb = blockIdx.z & 1, zn = blockIdx.z >> 1;
    A += (long long)zb * sAb + (long long)zn * sAn;
    B += (long long)zb * sBb + (long long)zn * sBn;
    C += (long long)zb * sCb + (long long)zn * sCn;

    const int lr = tid >> 3, lc4 = tid & 7;
    const __half* aptr[ACH];
    #pragma unroll
    for (int i = 0; i < ACH; i++)
        aptr[i] = A + (long long)(row0 + lr + i * 32) * lda + lc4 * 8;
    const __half* bptr[BCH];
    #pragma unroll
    for (int i = 0; i < BCH; i++)
        bptr[i] = B + (long long)(col0 + lr + i * 32) * ldb + lc4 * 8;

    const uint32_t s0   = smem_u32(smh);
    const uint32_t adst = (uint32_t)((lr * LDSW + lc4 * 8) * 2);
    const uint32_t bdst = (uint32_t)((STAGE_A + lr * LDSW + lc4 * 8) * 2);

    auto issue = [&](int s, int kb) {
        const uint32_t base = s0 + (uint32_t)s * STAGE_BYTES;
        #pragma unroll
        for (int i = 0; i < ACH; i++)
            cp16(base + adst + (uint32_t)(i * 32 * LDSW * 2), aptr[i] + kb);
        #pragma unroll
        for (int i = 0; i < BCH; i++)
            cp16(base + bdst + (uint32_t)(i * 32 * LDSW * 2), bptr[i] + kb);
        cp_commit();
    };

    const uint32_t a_lane_off =
        (uint32_t)(((wm0 + (lane & 15)) * LDSW + (lane >> 4) * 8) * 2);
    const uint32_t b_lane_off =
        (uint32_t)((STAGE_A + (wn0 + (lane & 7)) * LDSW + ((lane >> 3) & 1) * 8) * 2);

    float acc[MT][NT][4];
    #pragma unroll
    for (int m = 0; m < MT; m++)
        #pragma unroll
        for (int n = 0; n < NT; n++)
            #pragma unroll
            for (int q = 0; q < 4; q++) acc[m][n][q] = 0.0f;

    const int T = K >> 6;
    issue(0, 0);
    if (T > 1) issue(1, 64); else cp_commit();

    int st = 0;
    for (int t = 0; t < T; t++) {
        cp_wait<1>();
        __syncthreads();

        const uint32_t sbase = s0 + (uint32_t)st * STAGE_BYTES;
        const uint32_t abase = sbase + a_lane_off;
        const uint32_t bbase = sbase + b_lane_off;

        #pragma unroll
        for (int ks = 0; ks < 4; ks++) {
            uint32_t af[MT][4], bf[NT][2];
            #pragma unroll
            for (int m = 0; m < MT; m++)
                ldsm_x4(af[m], abase + (uint32_t)((m * 16 * LDSW + ks * 16) * 2));
            #pragma unroll
            for (int n = 0; n < NT; n++)
                ldsm_x2(bf[n], bbase + (uint32_t)((n * 8 * LDSW + ks * 16) * 2));
            #pragma unroll
            for (int m = 0; m < MT; m++)
                #pragma unroll
                for (int n = 0; n < NT; n++)
                    mma_f16(acc[m][n], af[m], bf[n]);
        }

        const int tn = t + 2;
        if (tn < T) issue(tn % 3, tn * 64); else cp_commit();
        st++; if (st == 3) st = 0;
    }

    #pragma unroll
    for (int m = 0; m < MT; m++) {
        const int r = row0 + wm0 + m * 16 + grp;
        #pragma unroll
        for (int n = 0; n < NT; n++) {
            const int c = col0 + wn0 + n * 8 + 2 * tig;
            if constexpr (sizeof(TC) == 4) {
                *(float2*)((float*)C + (long long)r * ldc + c)
                    = make_float2(acc[m][n][0], acc[m][n][1]);
                *(float2*)((float*)C + (long long)(r + 8) * ldc + c)
                    = make_float2(acc[m][n][2], acc[m][n][3]);
            } else {
                *(__half2*)((__half*)C + (long long)r * ldc + c)
                    = __floats2half2_rn(acc[m][n][0], acc[m][n][1]);
                *(__half2*)((__half*)C + (long long)(r + 8) * ldc + c)
                    = __floats2half2_rn(acc[m][n][2], acc[m][n][3]);
            }
        }
    }
}

// ======================= fp32 -> fp16 converts ==============================
__global__ void cvt_cat(const float* __restrict__ mems, const float* __restrict__ w,
                        __half* __restrict__ dst)
{
    const int i = blockIdx.x * 256 + threadIdx.x;          // float4 index
    const float4 v = (i < 524288) ? ((const float4*)mems)[i]
                                  : ((const float4*)w)[i - 524288];
    ((__half2*)dst)[2 * i]     = __floats2half2_rn(v.x, v.y);
    ((__half2*)dst)[2 * i + 1] = __floats2half2_rn(v.z, v.w);
}
__global__ void cvt_h(const float* __restrict__ src, __half* __restrict__ dst)
{
    const int i = blockIdx.x * 256 + threadIdx.x;
    const float4 v = ((const float4*)src)[i];
    ((__half2*)dst)[2 * i]     = __floats2half2_rn(v.x, v.y);
    ((__half2*)dst)[2 * i + 1] = __floats2half2_rn(v.z, v.w);
}

// ======================= transposes (fp32 in -> fp16 out) ===================
__global__ void transpose_kh(const float* __restrict__ src, __half* __restrict__ dst,
                             int rows, int cols)
{
    __shared__ float t[32][33];
    const int c0 = blockIdx.x * 32, r0 = blockIdx.y * 32;
    for (int i = threadIdx.y; i < 32; i += 8)
        t[i][threadIdx.x] = src[(long long)(r0 + i) * cols + c0 + threadIdx.x];
    __syncthreads();
    for (int i = threadIdx.y; i < 32; i += 8)
        dst[(long long)(c0 + i) * rows + r0 + threadIdx.x] = __float2half_rn(t[threadIdx.x][i]);
}

// VT16[z][d][j] = qkv16[(j*2+zb)*3072 + 2048 + zn*64 + d]
__global__ void vtrans_h(const __half* __restrict__ qkv, __half* __restrict__ vt)
{
    __shared__ __half t[32][34];
    const int j0 = blockIdx.x * 32;
    const int d0 = blockIdx.y * 32;
    const int z  = blockIdx.z;
    const int zb = z & 1, zn = z >> 1;
    for (int i = threadIdx.y; i < 32; i += 8)
        t[i][threadIdx.x] =
            qkv[(long long)((j0 + i) * 2 + zb) * 3072 + 2048 + zn * 64 + d0 + threadIdx.x];
    __syncthreads();
    __half* dst = vt + (long long)z * 64 * 2048;
    for (int i = threadIdx.y; i < 32; i += 8)
        dst[(long long)(d0 + i) * 2048 + j0 + threadIdx.x] = t[threadIdx.x][i];
}

// ======================= rank-1 bias dots ===================================
__global__ void bias_dot(const float* __restrict__ rwb, const float* __restrict__ rrb)
{
    const int gw   = blockIdx.x * 8 + (threadIdx.x >> 5);
    const int lane = threadIdx.x & 31;
    const int kind = blockIdx.y;
    const int z = gw >> 11, j = gw & 2047;
    const int zb = z & 1, zn = z >> 1;
    const float* bias = (kind ? rrb : rwb) + zn * 64;
    const __half* row = kind
        ? (const __half*)(g_scratch + OFF_RK16)  + (long long)j * 1024 + zn * 64
        : (const __half*)(g_scratch + OFF_QKV16) + (long long)(j * 2 + zb) * 3072 + 1024 + zn * 64;
    float s = __half2float(row[lane]) * bias[lane]
            + __half2float(row[lane + 32]) * bias[lane + 32];
    #pragma unroll
    for (int o = 16; o; o >>= 1) s += __shfl_xor_sync(0xffffffffu, s, o);
    if (lane == 0)
        g_scratch[(kind ? OFF_BDB : OFF_ACB) + (long long)z * 2048 + j] = s;
}

// ======================= shift + bias + mask + softmax (in place, fp16) =====
__global__ void __launch_bounds__(256) softmax_kernel()
{
    const int i = blockIdx.x;
    const int z = blockIdx.y;
    __half*       srow = (__half*)(g_scratch + OFF_S16)  + (long long)z * QLEN * KLEN + (long long)i * KLEN;
    const __half* brow = (const __half*)(g_scratch + OFF_BD16) + (long long)z * QLEN * KLEN + (long long)i * KLEN;
    const float* acb = g_scratch + OFF_ACB + (long long)z * 2048;
    const float* bdb = g_scratch + OFF_BDB + (long long)z * 2048;
    const int limit = i + MEMLEN;                      // inclusive valid bound
    const int jmax  = min((i & ~127) + 1152, KLEN);    // PV never reads beyond this
    const int tid = threadIdx.x;

    float v[8];
    float lmax = -1e30f;
    #pragma unroll
    for (int u = 0; u < 8; u++) {
        const int j = tid + u * 256;
        if (j <= limit) {
            const int p = j - i + (QLEN - 1);
            const float val = (__half2float(srow[j]) + acb[j]
                             + __half2float(brow[p]) + bdb[p]) * 0.125f;
            v[u] = val;
            lmax = fmaxf(lmax, val);
        } else {
            v[u] = -3.0e38f;
        }
    }
    __shared__ float red[256];
    red[tid] = lmax; __syncthreads();
    for (int s = 128; s; s >>= 1) { if (tid < s) red[tid] = fmaxf(red[tid], red[tid + s]); __syncthreads(); }
    const float m = red[0];
    __syncthreads();

    float lsum = 0.0f;
    #pragma unroll
    for (int u = 0; u < 8; u++) {
        const float e = expf(v[u] - m);                // masked lanes -> exactly 0
        v[u] = e; lsum += e;
    }
    red[tid] = lsum; __syncthreads();
    for (int s = 128; s; s >>= 1) { if (tid < s) red[tid] += red[tid + s]; __syncthreads(); }
    const float inv = 1.0f / red[0];

    #pragma unroll
    for (int u = 0; u < 8; u++) {
        const int j = tid + u * 256;
        if (j < jmax) srow[j] = __float2half_rn(v[u] * inv);   // probs in place
    }
}

// ======================= residual + LayerNorm ===============================
__global__ void __launch_bounds__(256) ln_kernel(
    const float* __restrict__ w,
    const float* __restrict__ gamma,
    const float* __restrict__ beta,
    float* __restrict__ out)
{
    const int row = blockIdx.x;
    const float* wr = w + (long long)row * DM;
    const float* ar = g_scratch + OFF_AO + (long long)row * DM;
    const int tid = threadIdx.x;

    float y[4];
    float s = 0.0f, s2 = 0.0f;
    #pragma unroll
    for (int u = 0; u < 4; u++) {
        const int c = tid + u * 256;
        y[u] = wr[c] + ar[c];
        s += y[u]; s2 += y[u] * y[u];
    }
    __shared__ float rs[256], rs2[256];
    rs[tid] = s; rs2[tid] = s2; __syncthreads();
    for (int st = 128; st; st >>= 1) {
        if (tid < st) { rs[tid] += rs[tid + st]; rs2[tid] += rs2[tid + st]; }
        __syncthreads();
    }
    const float mu   = rs[0]  * (1.0f / 1024.0f);
    const float var  = rs2[0] * (1.0f / 1024.0f) - mu * mu;
    const float rstd = rsqrtf(var + 1e-5f);
    #pragma unroll
    for (int u = 0; u < 4; u++) {
        const int c = tid + u * 256;
        out[(long long)row * DM + c] = (y[u] - mu) * rstd * gamma[c] + beta[c];
    }
}

// ======================= launch =============================================
extern "C" void kernel_launch(void* const* d_in, const int* in_sizes, int n_in,
                              void* d_out, int out_size)
{
    (void)in_sizes; (void)n_in; (void)out_size;
    const float* w     = (const float*)d_in[0];   // [1024,2,1024]
    const float* r     = (const float*)d_in[1];   // [2048,1024]
    const float* rwb   = (const float*)d_in[2];   // [16,64]
    const float* rrb   = (const float*)d_in[3];   // [16,64]
    const float* mems  = (const float*)d_in[4];   // [1024,2,1024]
    /* d_in[5] = attn_mask (deterministic, unused) */
    const float* Wqkv  = (const float*)d_in[6];   // [1024,3072]
    const float* Wr    = (const float*)d_in[7];   // [1024,1024]
    const float* Wo    = (const float*)d_in[8];   // [1024,1024]
    const float* gamma = (const float*)d_in[9];
    const float* beta  = (const float*)d_in[10];
    float* out = (float*)d_out;

    float* g = nullptr;
    cudaGetSymbolAddress((void**)&g, g_scratch);
    __half* qkv16 = (__half*)(g + OFF_QKV16);
    __half* rk16  = (__half*)(g + OFF_RK16);
    __half* cat16 = (__half*)(g + OFF_CAT16);
    __half* r16   = (__half*)(g + OFF_R16);
    __half* s16   = (__half*)(g + OFF_S16);
    __half* bd16  = (__half*)(g + OFF_BD16);
    __half* av16  = (__half*)(g + OFF_AV16);
    __half* wqkvt = (__half*)(g + OFF_WQKVT);
    __half* wrt   = (__half*)(g + OFF_WRT);
    __half* wot   = (__half*)(g + OFF_WOT);
    __half* vt16  = (__half*)(g + OFF_VT16);

    constexpr int SM128 = 3 * (128 + 128) * 72 * 2;   // 110,592 B
    constexpr int SM64  = 3 * (128 + 64)  * 72 * 2;   //  82,944 B
    static bool attr_done = false;
    if (!attr_done) {
        cudaFuncSetAttribute((void*)gemm_h<128, float>,  cudaFuncAttributeMaxDynamicSharedMemorySize, SM128);
        cudaFuncSetAttribute((void*)gemm_h<128, __half>, cudaFuncAttributeMaxDynamicSharedMemorySize, SM128);
        cudaFuncSetAttribute((void*)gemm_h<64,  __half>, cudaFuncAttributeMaxDynamicSharedMemorySize, SM64);
        attr_done = true;
    }

    dim3 tb(32, 8);

    // 0) fp16 conversions + weight transposes
    cvt_cat<<<4096, 256>>>(mems, w, cat16);
    cvt_h<<<2048, 256>>>(r, r16);
    transpose_kh<<<dim3(96, 32), tb>>>(Wqkv, wqkvt, 1024, 3072);
    transpose_kh<<<dim3(32, 32), tb>>>(Wr,   wrt,   1024, 1024);
    transpose_kh<<<dim3(32, 32), tb>>>(Wo,   wot,   1024, 1024);

    // 1) QKV projection -> fp16
    gemm_h<128, __half><<<dim3(24, 32, 1), 256, SM128>>>(
        cat16, 1024, 0, 0,
        wqkvt, 1024, 0, 0,
        qkv16, 3072, 0, 0, 1024, 0);

    // 2) R projection -> fp16
    gemm_h<128, __half><<<dim3(8, 16, 1), 256, SM128>>>(
        r16, 1024, 0, 0,
        wrt, 1024, 0, 0,
        rk16, 1024, 0, 0, 1024, 0);

    // 3) rank-1 bias terms
    bias_dot<<<dim3(8192, 2), 256>>>(rwb, rrb);

    // 4) AC = Q @ K^T -> fp16 scores  (z = n*2 + b; masked-tile skip)
    gemm_h<128, __half><<<dim3(16, 8, 32), 256, SM128>>>(
        qkv16 + 2048LL * 3072, 6144, 3072, 64,
        qkv16 + 1024,          6144, 3072, 64,
        s16, 2048, 2097152LL, 4194304LL, 64, 1);

    // 5) BD_pre = Q @ RK^T -> fp16  (unused-tile skip)
    gemm_h<128, __half><<<dim3(16, 8, 32), 256, SM128>>>(
        qkv16 + 2048LL * 3072, 6144, 3072, 64,
        rk16,                  1024, 0,    64,
        bd16, 2048, 2097152LL, 4194304LL, 64, 2);

    // 6) shift + bias + mask + softmax (fp16 in, fp16 probs in place)
    softmax_kernel<<<dim3(1024, 32), 256>>>();

    // 7) V transpose -> fp16 [z][64][2048]
    vtrans_h<<<dim3(64, 2, 32), tb>>>(qkv16, vt16);

    // 8) attn_vec = P @ V -> fp16 (K capped per M-block)
    gemm_h<64, __half><<<dim3(1, 8, 32), 256, SM64>>>(
        s16,  2048, 2097152LL, 4194304LL,
        vt16, 2048, 131072LL,  262144LL,
        av16, 2048, 1024LL, 64LL, 2048, 3);

    // 9) output projection -> fp32
    gemm_h<128, float><<<dim3(8, 16, 1), 256, SM128>>>(
        av16, 1024, 0, 0,
        wot,  1024, 0, 0,
        g + OFF_AO, 1024, 0, 0, 1024, 0);

    // 10) residual + LayerNorm
    ln_kernel<<<2048, 256>>>(w, gamma, beta, out);
}

// round 8
// speedup vs baseline: 10.3298x; 1.1964x over previous
#include <cuda_runtime.h>
#include <cuda_fp16.h>
#include <cstdint>
#include <math.h>

#define QLEN   1024
#define MEMLEN 1024
#define KLEN   2048
#define DM     1024

// ======================= scratch (units: floats) ============================
static constexpr long long OFF_QKV16 = 0;                            // half [4096][3072]
static constexpr long long OFF_RK16  = OFF_QKV16 + 6291456LL;        // half [2048][1024]
static constexpr long long OFF_CAT16 = OFF_RK16  + 1048576LL;        // half [4096][1024]
static constexpr long long OFF_R16   = OFF_CAT16 + 2097152LL;        // half [2048][1024]
static constexpr long long OFF_BD16  = OFF_R16   + 1048576LL;        // half [32][1024][2048] BD_pre (+colbias)
static constexpr long long OFF_AV16  = OFF_BD16  + 33554432LL;       // half [1024][2][1024]
static constexpr long long OFF_AO    = OFF_AV16  + 1048576LL;        // f32  [2048][1024]
static constexpr long long OFF_WQKVT = OFF_AO    + 2097152LL;        // half [3072][1024]
static constexpr long long OFF_WRT   = OFF_WQKVT + 1572864LL;        // half [1024][1024]
static constexpr long long OFF_WOT   = OFF_WRT   + 524288LL;         // half [1024][1024]
static constexpr long long OFF_VT16  = OFF_WOT   + 524288LL;         // half [32][64][2048]
static constexpr long long OFF_ACB   = OFF_VT16  + 2097152LL;        // f32  [32][2048]
static constexpr long long OFF_BDB   = OFF_ACB   + 65536LL;          // f32  [32][2048]
static constexpr long long SCRATCH_TOTAL = OFF_BDB + 65536LL;

__device__ float g_scratch[SCRATCH_TOTAL];

// ======================= helpers ============================================
__device__ __forceinline__ uint32_t smem_u32(const void* p) {
    uint32_t a;
    asm("{ .reg .u64 t; cvta.to.shared.u64 t, %1; cvt.u32.u64 %0, t; }" : "=r"(a) : "l"(p));
    return a;
}
__device__ __forceinline__ void cp16(uint32_t s, const void* g) {
    asm volatile("cp.async.cg.shared.global [%0], [%1], 16;" :: "r"(s), "l"(g));
}
__device__ __forceinline__ void cp_commit() {
    asm volatile("cp.async.commit_group;");
}
template<int N> __device__ __forceinline__ void cp_wait() {
    asm volatile("cp.async.wait_group %0;" :: "n"(N));
}
__device__ __forceinline__ void mma_f16(float* c, const uint32_t* a, const uint32_t* b)
{
    asm volatile(
        "mma.sync.aligned.m16n8k16.row.col.f32.f16.f16.f32 "
        "{%0,%1,%2,%3}, {%4,%5,%6,%7}, {%8,%9}, {%0,%1,%2,%3};"
        : "+f"(c[0]), "+f"(c[1]), "+f"(c[2]), "+f"(c[3])
        : "r"(a[0]), "r"(a[1]), "r"(a[2]), "r"(a[3]), "r"(b[0]), "r"(b[1]));
}
__device__ __forceinline__ void ldsm_x4(uint32_t* r, uint32_t addr) {
    asm volatile("ldmatrix.sync.aligned.m8n8.x4.shared.b16 {%0,%1,%2,%3}, [%4];"
        : "=r"(r[0]), "=r"(r[1]), "=r"(r[2]), "=r"(r[3]) : "r"(addr));
}
__device__ __forceinline__ void ldsm_x2(uint32_t* r, uint32_t addr) {
    asm volatile("ldmatrix.sync.aligned.m8n8.x2.shared.b16 {%0,%1}, [%2];"
        : "=r"(r[0]), "=r"(r[1]) : "r"(addr));
}
__device__ __forceinline__ uint32_t packh2(float a, float b) {
    __half2 h = __floats2half2_rn(a, b);
    return *(uint32_t*)&h;
}

// ======================= pipelined fp16 NT GEMM =============================
// C[M,N] = A[M,K] @ B[N,K]^T ; fp16 operands k-contiguous in gmem, fp32 accum.
// colbias (optional, fp32, stride 2048 per z) added per output column.
// skipmode: 0 none; 2 skip never-read BD_pre tiles.
template<int BN, typename TC>
__global__ void __launch_bounds__(256, 2) gemm_h(
    const __half* __restrict__ A, int lda, long long sAb, long long sAn,
    const __half* __restrict__ B, int ldb, long long sBb, long long sBn,
    TC* __restrict__ C, int ldc, long long sCb, long long sCn,
    int K, int skipmode, const float* __restrict__ colbias)
{
    constexpr int BM = 128, LDSW = 72;
    constexpr int STAGE_A = BM * LDSW;
    constexpr int STAGE_B = BN * LDSW;
    constexpr uint32_t STAGE_BYTES = (STAGE_A + STAGE_B) * 2;
    constexpr int ACH = BM / 32;
    constexpr int BCH = BN / 32;
    constexpr int WCOLS = (BN == 128) ? 4 : 2;
    constexpr int WROWS = 8 / WCOLS;
    constexpr int WM = BM / WROWS, WN = BN / WCOLS;
    constexpr int MT = WM / 16, NT = WN / 8;

    const int row0 = blockIdx.y * BM;
    const int col0 = blockIdx.x * BN;
    if (skipmode == 2 && col0 + BN - 1 < (QLEN - 1) - (row0 + BM - 1)) return;

    extern __shared__ __half smh[];
    const int tid = threadIdx.x, wid = tid >> 5, lane = tid & 31;
    const int grp = lane >> 2, tig = lane & 3;
    const int wr = wid / WCOLS, wc = wid % WCOLS;
    const int wm0 = wr * WM, wn0 = wc * WN;

    const int zb = blockIdx.z & 1, zn = blockIdx.z >> 1;
    A += (long long)zb * sAb + (long long)zn * sAn;
    B += (long long)zb * sBb + (long long)zn * sBn;
    C += (long long)zb * sCb + (long long)zn * sCn;
    const float* cbz = colbias ? colbias + (long long)blockIdx.z * 2048 : nullptr;

    const int lr = tid >> 3, lc4 = tid & 7;
    const __half* aptr[ACH];
    #pragma unroll
    for (int i = 0; i < ACH; i++)
        aptr[i] = A + (long long)(row0 + lr + i * 32) * lda + lc4 * 8;
    const __half* bptr[BCH];
    #pragma unroll
    for (int i = 0; i < BCH; i++)
        bptr[i] = B + (long long)(col0 + lr + i * 32) * ldb + lc4 * 8;

    const uint32_t s0   = smem_u32(smh);
    const uint32_t adst = (uint32_t)((lr * LDSW + lc4 * 8) * 2);
    const uint32_t bdst = (uint32_t)((STAGE_A + lr * LDSW + lc4 * 8) * 2);

    auto issue = [&](int s, int kb) {
        const uint32_t base = s0 + (uint32_t)s * STAGE_BYTES;
        #pragma unroll
        for (int i = 0; i < ACH; i++)
            cp16(base + adst + (uint32_t)(i * 32 * LDSW * 2), aptr[i] + kb);
        #pragma unroll
        for (int i = 0; i < BCH; i++)
            cp16(base + bdst + (uint32_t)(i * 32 * LDSW * 2), bptr[i] + kb);
        cp_commit();
    };

    const uint32_t a_lane_off =
        (uint32_t)(((wm0 + (lane & 15)) * LDSW + (lane >> 4) * 8) * 2);
    const uint32_t b_lane_off =
        (uint32_t)((STAGE_A + (wn0 + (lane & 7)) * LDSW + ((lane >> 3) & 1) * 8) * 2);

    float acc[MT][NT][4];
    #pragma unroll
    for (int m = 0; m < MT; m++)
        #pragma unroll
        for (int n = 0; n < NT; n++)
            #pragma unroll
            for (int q = 0; q < 4; q++) acc[m][n][q] = 0.0f;

    const int T = K >> 6;
    issue(0, 0);
    if (T > 1) issue(1, 64); else cp_commit();

    int st = 0;
    for (int t = 0; t < T; t++) {
        cp_wait<1>();
        __syncthreads();

        const uint32_t sbase = s0 + (uint32_t)st * STAGE_BYTES;
        const uint32_t abase = sbase + a_lane_off;
        const uint32_t bbase = sbase + b_lane_off;

        #pragma unroll
        for (int ks = 0; ks < 4; ks++) {
            uint32_t af[MT][4], bf[NT][2];
            #pragma unroll
            for (int m = 0; m < MT; m++)
                ldsm_x4(af[m], abase + (uint32_t)((m * 16 * LDSW + ks * 16) * 2));
            #pragma unroll
            for (int n = 0; n < NT; n++)
                ldsm_x2(bf[n], bbase + (uint32_t)((n * 8 * LDSW + ks * 16) * 2));
            #pragma unroll
            for (int m = 0; m < MT; m++)
                #pragma unroll
                for (int n = 0; n < NT; n++)
                    mma_f16(acc[m][n], af[m], bf[n]);
        }

        const int tn = t + 2;
        if (tn < T) issue(tn % 3, tn * 64); else cp_commit();
        st++; if (st == 3) st = 0;
    }

    #pragma unroll
    for (int m = 0; m < MT; m++) {
        const int r = row0 + wm0 + m * 16 + grp;
        #pragma unroll
        for (int n = 0; n < NT; n++) {
            const int c = col0 + wn0 + n * 8 + 2 * tig;
            float c0 = acc[m][n][0], c1 = acc[m][n][1];
            float c2 = acc[m][n][2], c3 = acc[m][n][3];
            if (cbz) { c0 += cbz[c]; c1 += cbz[c + 1]; c2 += cbz[c]; c3 += cbz[c + 1]; }
            if constexpr (sizeof(TC) == 4) {
                *(float2*)((float*)C + (long long)r * ldc + c)       = make_float2(c0, c1);
                *(float2*)((float*)C + (long long)(r + 8) * ldc + c) = make_float2(c2, c3);
            } else {
                *(__half2*)((__half*)C + (long long)r * ldc + c)       = __floats2half2_rn(c0, c1);
                *(__half2*)((__half*)C + (long long)(r + 8) * ldc + c) = __floats2half2_rn(c2, c3);
            }
        }
    }
}

// ======================= flash attention kernel =============================
// One CTA per (q-block of 128 rows, z). Computes S = Q K^T per 128-col j-tile,
// adds shifted BD_pre (+acb), online softmax, accumulates P@V in registers.
__global__ void __launch_bounds__(256, 1) flash_kernel(
    const __half* __restrict__ qkv16, const __half* __restrict__ vt16,
    const __half* __restrict__ bd16, const float* __restrict__ acb,
    __half* __restrict__ av16)
{
    constexpr int LQ = 72, LV = 136;
    constexpr int QH = 128 * LQ;          // Q tile halves
    constexpr int KH = 128 * LQ;          // K stage halves
    constexpr int VH = 64 * LV;           // V stage halves
    constexpr int K_OFF   = QH;
    constexpr int V_OFF   = QH + 3 * KH;
    constexpr int ACB_OFF = V_OFF + 3 * VH;   // halves; 256 halves (=128 floats) per stage

    extern __shared__ __half smh[];
    const int tid = threadIdx.x, wid = tid >> 5, lane = tid & 31;
    const int grp = lane >> 2, tig = lane & 3;
    const int qb = blockIdx.x, z = blockIdx.y;
    const int zb = z & 1, zn = z >> 1;
    const int row0 = qb * 128;

    const __half* Qg  = qkv16 + 2048LL * 3072 + zb * 3072 + zn * 64;
    const __half* Kg  = qkv16 + 1024 + zb * 3072 + zn * 64;
    const __half* Vg  = vt16 + (long long)z * 131072;
    const __half* bdz = bd16 + (long long)zb * 2097152 + (long long)zn * 4194304;
    const float*  acz = acb + (long long)z * 2048;

    const uint32_t s0 = smem_u32(smh);
    const int T = qb + 9;                 // j-tiles: j < row0 + 1152

    const int lr8 = tid >> 3, lc8 = tid & 7;      // 128 rows x 8 chunks
    const int lr16 = tid >> 4, lc16 = tid & 15;   // 64 rows x 16 chunks

    auto issueQ = [&]() {
        #pragma unroll
        for (int i2 = 0; i2 < 4; i2++) {
            const int r = lr8 + i2 * 32;
            cp16(s0 + (uint32_t)((r * LQ + lc8 * 8) * 2),
                 Qg + (long long)(row0 + r) * 6144 + lc8 * 8);
        }
    };
    auto issueT = [&](int t) {
        const int stg = t % 3;
        const int jt0 = t * 128;
        const uint32_t kb = s0 + (uint32_t)((K_OFF + stg * KH) * 2);
        #pragma unroll
        for (int i2 = 0; i2 < 4; i2++) {
            const int r = lr8 + i2 * 32;
            cp16(kb + (uint32_t)((r * LQ + lc8 * 8) * 2),
                 Kg + (long long)(jt0 + r) * 6144 + lc8 * 8);
        }
        const uint32_t vb = s0 + (uint32_t)((V_OFF + stg * VH) * 2);
        #pragma unroll
        for (int i2 = 0; i2 < 4; i2++) {
            const int r = lr16 + i2 * 16;
            cp16(vb + (uint32_t)((r * LV + lc16 * 8) * 2),
                 Vg + (long long)r * 2048 + jt0 + lc16 * 8);
        }
        if (tid < 32)
            cp16(s0 + (uint32_t)((ACB_OFF + stg * 256) * 2) + (uint32_t)(tid * 16),
                 acz + jt0 + tid * 4);
    };

    issueQ(); issueT(0); cp_commit();
    issueT(1); cp_commit();
    cp_wait<1>(); __syncthreads();

    // preload Q fragments (resident for whole kernel)
    const uint32_t a_off =
        (uint32_t)(((wid * 16 + (lane & 15)) * LQ + (lane >> 4) * 8) * 2);
    uint32_t afq[4][4];
    #pragma unroll
    for (int ks = 0; ks < 4; ks++)
        ldsm_x4(afq[ks], s0 + a_off + (uint32_t)(ks * 16 * 2));

    const int i_lo = row0 + wid * 16 + grp;
    const int i_hi = i_lo + 8;
    const __half* brow_lo = bdz + (long long)i_lo * 2048;
    const __half* brow_hi = bdz + (long long)i_hi * 2048;

    // B-fragment x4 lane addressing (2 n-tiles per ldsm_x4)
    const int bg = lane >> 3;
    const int b_row_sub = ((bg >> 1) & 1) * 8 + (lane & 7);
    const int b_col_sub = (bg & 1) * 8;

    float m_lo = -1e30f, m_hi = -1e30f, l_lo = 0.f, l_hi = 0.f;
    float acc_o[8][4];
    #pragma unroll
    for (int n = 0; n < 8; n++)
        #pragma unroll
        for (int q = 0; q < 4; q++) acc_o[n][q] = 0.f;

    for (int t = 0; t < T; t++) {
        if (t > 0) { cp_wait<1>(); __syncthreads(); }
        const int stg = t % 3, jt0 = t * 128;
        const uint32_t kbase = s0 + (uint32_t)((K_OFF + stg * KH) * 2);
        const uint32_t vbase = s0 + (uint32_t)((V_OFF + stg * VH) * 2);
        const float* acbs = (const float*)(smh + ACB_OFF + stg * 256);

        // ---- S = Q @ K_tile^T ----
        float acc_s[16][4];
        #pragma unroll
        for (int n = 0; n < 16; n++)
            #pragma unroll
            for (int q = 0; q < 4; q++) acc_s[n][q] = 0.f;

        #pragma unroll
        for (int ks = 0; ks < 4; ks++) {
            #pragma unroll
            for (int n2 = 0; n2 < 8; n2++) {
                uint32_t bf[4];
                ldsm_x4(bf, kbase + (uint32_t)(((n2 * 16 + b_row_sub) * LQ + ks * 16 + b_col_sub) * 2));
                mma_f16(acc_s[2 * n2],     afq[ks], bf);
                mma_f16(acc_s[2 * n2 + 1], afq[ks], bf + 2);
            }
        }

        // ---- scores: + acb + shifted BD, mask, scale ----
        float tmax_lo = -1e30f, tmax_hi = -1e30f;
        #pragma unroll
        for (int n = 0; n < 16; n++) {
            const int jc = n * 8 + 2 * tig;
            const int jq = jt0 + jc;
            const float a0 = acbs[jc], a1 = acbs[jc + 1];
            const int p0 = jq - i_lo + (QLEN - 1);
            const int p2 = jq - i_hi + (QLEN - 1);
            float v0 = (acc_s[n][0] + a0 + __half2float(brow_lo[min(p0, 2047)])) * 0.125f;
            float v1 = (acc_s[n][1] + a1 + __half2float(brow_lo[min(p0 + 1, 2047)])) * 0.125f;
            float v2 = (acc_s[n][2] + a0 + __half2float(brow_hi[min(p2, 2047)])) * 0.125f;
            float v3 = (acc_s[n][3] + a1 + __half2float(brow_hi[min(p2 + 1, 2047)])) * 0.125f;
            if (jq     > i_lo + MEMLEN) v0 = -1e30f;
            if (jq + 1 > i_lo + MEMLEN) v1 = -1e30f;
            if (jq     > i_hi + MEMLEN) v2 = -1e30f;
            if (jq + 1 > i_hi + MEMLEN) v3 = -1e30f;
            acc_s[n][0] = v0; acc_s[n][1] = v1; acc_s[n][2] = v2; acc_s[n][3] = v3;
            tmax_lo = fmaxf(tmax_lo, fmaxf(v0, v1));
            tmax_hi = fmaxf(tmax_hi, fmaxf(v2, v3));
        }
        tmax_lo = fmaxf(tmax_lo, __shfl_xor_sync(0xffffffffu, tmax_lo, 1));
        tmax_lo = fmaxf(tmax_lo, __shfl_xor_sync(0xffffffffu, tmax_lo, 2));
        tmax_hi = fmaxf(tmax_hi, __shfl_xor_sync(0xffffffffu, tmax_hi, 1));
        tmax_hi = fmaxf(tmax_hi, __shfl_xor_sync(0xffffffffu, tmax_hi, 2));

        const float mn_lo = fmaxf(m_lo, tmax_lo);
        const float mn_hi = fmaxf(m_hi, tmax_hi);
        const float cor_lo = __expf(m_lo - mn_lo);
        const float cor_hi = __expf(m_hi - mn_hi);
        m_lo = mn_lo; m_hi = mn_hi;

        float sum_lo = 0.f, sum_hi = 0.f;
        uint32_t pf[16][2];
        #pragma unroll
        for (int n = 0; n < 16; n++) {
            const float e0 = __expf(acc_s[n][0] - mn_lo);
            const float e1 = __expf(acc_s[n][1] - mn_lo);
            const float e2 = __expf(acc_s[n][2] - mn_hi);
            const float e3 = __expf(acc_s[n][3] - mn_hi);
            sum_lo += e0 + e1; sum_hi += e2 + e3;
            pf[n][0] = packh2(e0, e1);
            pf[n][1] = packh2(e2, e3);
        }
        sum_lo += __shfl_xor_sync(0xffffffffu, sum_lo, 1);
        sum_lo += __shfl_xor_sync(0xffffffffu, sum_lo, 2);
        sum_hi += __shfl_xor_sync(0xffffffffu, sum_hi, 1);
        sum_hi += __shfl_xor_sync(0xffffffffu, sum_hi, 2);
        l_lo = l_lo * cor_lo + sum_lo;
        l_hi = l_hi * cor_hi + sum_hi;

        #pragma unroll
        for (int n = 0; n < 8; n++) {
            acc_o[n][0] *= cor_lo; acc_o[n][1] *= cor_lo;
            acc_o[n][2] *= cor_hi; acc_o[n][3] *= cor_hi;
        }

        // ---- O += P_tile @ V_tile  (P fragments straight from registers) ----
        #pragma unroll
        for (int kk = 0; kk < 8; kk++) {
            const uint32_t a[4] = { pf[2 * kk][0], pf[2 * kk][1],
                                    pf[2 * kk + 1][0], pf[2 * kk + 1][1] };
            #pragma unroll
            for (int n2 = 0; n2 < 4; n2++) {
                uint32_t bf[4];
                ldsm_x4(bf, vbase + (uint32_t)(((n2 * 16 + b_row_sub) * LV + kk * 16 + b_col_sub) * 2));
                mma_f16(acc_o[2 * n2],     a, bf);
                mma_f16(acc_o[2 * n2 + 1], a, bf + 2);
            }
        }

        if (t + 2 < T) issueT(t + 2);
        cp_commit();
    }

    // ---- epilogue: normalize, write av16 ----
    const float il_lo = 1.f / l_lo, il_hi = 1.f / l_hi;
    __half* av_lo = av16 + (long long)i_lo * 2048 + zb * 1024 + zn * 64;
    __half* av_hi = av16 + (long long)i_hi * 2048 + zb * 1024 + zn * 64;
    #pragma unroll
    for (int n = 0; n < 8; n++) {
        const int c = n * 8 + 2 * tig;
        *(__half2*)(av_lo + c) = __floats2half2_rn(acc_o[n][0] * il_lo, acc_o[n][1] * il_lo);
        *(__half2*)(av_hi + c) = __floats2half2_rn(acc_o[n][2] * il_hi, acc_o[n][3] * il_hi);
    }
}

// ======================= fp32 -> fp16 converts ==============================
__global__ void cvt_cat(const float* __restrict__ mems, const float* __restrict__ w,
                        __half* __restrict__ dst)
{
    const int i = blockIdx.x * 256 + threadIdx.x;
    const float4 v = (i < 524288) ? ((const float4*)mems)[i]
                                  : ((const float4*)w)[i - 524288];
    ((__half2*)dst)[2 * i]     = __floats2half2_rn(v.x, v.y);
    ((__half2*)dst)[2 * i + 1] = __floats2half2_rn(v.z, v.w);
}
__global__ void cvt_h(const float* __restrict__ src, __half* __restrict__ dst)
{
    const int i = blockIdx.x * 256 + threadIdx.x;
    const float4 v = ((const float4*)src)[i];
    ((__half2*)dst)[2 * i]     = __floats2half2_rn(v.x, v.y);
    ((__half2*)dst)[2 * i + 1] = __floats2half2_rn(v.z, v.w);
}

// ======================= transposes (fp32 in -> fp16 out) ===================
__global__ void transpose_kh(const float* __restrict__ src, __half* __restrict__ dst,
                             int rows, int cols)
{
    __shared__ float t[32][33];
    const int c0 = blockIdx.x * 32, r0 = blockIdx.y * 32;
    for (int i = threadIdx.y; i < 32; i += 8)
        t[i][threadIdx.x] = src[(long long)(r0 + i) * cols + c0 + threadIdx.x];
    __syncthreads();
    for (int i = threadIdx.y; i < 32; i += 8)
        dst[(long long)(c0 + i) * rows + r0 + threadIdx.x] = __float2half_rn(t[threadIdx.x][i]);
}

// VT16[z][d][j] = qkv16[(j*2+zb)*3072 + 2048 + zn*64 + d]
__global__ void vtrans_h(const __half* __restrict__ qkv, __half* __restrict__ vt)
{
    __shared__ __half t[32][34];
    const int j0 = blockIdx.x * 32;
    const int d0 = blockIdx.y * 32;
    const int z  = blockIdx.z;
    const int zb = z & 1, zn = z >> 1;
    for (int i = threadIdx.y; i < 32; i += 8)
        t[i][threadIdx.x] =
            qkv[(long long)((j0 + i) * 2 + zb) * 3072 + 2048 + zn * 64 + d0 + threadIdx.x];
    __syncthreads();
    __half* dst = vt + (long long)z * 64 * 2048;
    for (int i = threadIdx.y; i < 32; i += 8)
        dst[(long long)(d0 + i) * 2048 + j0 + threadIdx.x] = t[threadIdx.x][i];
}

// ======================= rank-1 bias dots ===================================
__global__ void bias_dot(const float* __restrict__ rwb, const float* __restrict__ rrb)
{
    const int gw   = blockIdx.x * 8 + (threadIdx.x >> 5);
    const int lane = threadIdx.x & 31;
    const int kind = blockIdx.y;
    const int z = gw >> 11, j = gw & 2047;
    const int zb = z & 1, zn = z >> 1;
    const float* bias = (kind ? rrb : rwb) + zn * 64;
    const __half* row = kind
        ? (const __half*)(g_scratch + OFF_RK16)  + (long long)j * 1024 + zn * 64
        : (const __half*)(g_scratch + OFF_QKV16) + (long long)(j * 2 + zb) * 3072 + 1024 + zn * 64;
    float s = __half2float(row[lane]) * bias[lane]
            + __half2float(row[lane + 32]) * bias[lane + 32];
    #pragma unroll
    for (int o = 16; o; o >>= 1) s += __shfl_xor_sync(0xffffffffu, s, o);
    if (lane == 0)
        g_scratch[(kind ? OFF_BDB : OFF_ACB) + (long long)z * 2048 + j] = s;
}

// ======================= residual + LayerNorm ===============================
__global__ void __launch_bounds__(256) ln_kernel(
    const float* __restrict__ w,
    const float* __restrict__ gamma,
    const float* __restrict__ beta,
    float* __restrict__ out)
{
    const int row = blockIdx.x;
    const float* wr = w + (long long)row * DM;
    const float* ar = g_scratch + OFF_AO + (long long)row * DM;
    const int tid = threadIdx.x;

    float y[4];
    float s = 0.0f, s2 = 0.0f;
    #pragma unroll
    for (int u = 0; u < 4; u++) {
        const int c = tid + u * 256;
        y[u] = wr[c] + ar[c];
        s += y[u]; s2 += y[u] * y[u];
    }
    __shared__ float rs[256], rs2[256];
    rs[tid] = s; rs2[tid] = s2; __syncthreads();
    for (int st = 128; st; st >>= 1) {
        if (tid < st) { rs[tid] += rs[tid + st]; rs2[tid] += rs2[tid + st]; }
        __syncthreads();
    }
    const float mu   = rs[0]  * (1.0f / 1024.0f);
    const float var  = rs2[0] * (1.0f / 1024.0f) - mu * mu;
    const float rstd = rsqrtf(var + 1e-5f);
    #pragma unroll
    for (int u = 0; u < 4; u++) {
        const int c = tid + u * 256;
        out[(long long)row * DM + c] = (y[u] - mu) * rstd * gamma[c] + beta[c];
    }
}

// ======================= launch =============================================
extern "C" void kernel_launch(void* const* d_in, const int* in_sizes, int n_in,
                              void* d_out, int out_size)
{
    (void)in_sizes; (void)n_in; (void)out_size;
    const float* w     = (const float*)d_in[0];
    const float* r     = (const float*)d_in[1];
    const float* rwb   = (const float*)d_in[2];
    const float* rrb   = (const float*)d_in[3];
    const float* mems  = (const float*)d_in[4];
    /* d_in[5] = attn_mask (deterministic, unused) */
    const float* Wqkv  = (const float*)d_in[6];
    const float* Wr    = (const float*)d_in[7];
    const float* Wo    = (const float*)d_in[8];
    const float* gamma = (const float*)d_in[9];
    const float* beta  = (const float*)d_in[10];
    float* out = (float*)d_out;

    float* g = nullptr;
    cudaGetSymbolAddress((void**)&g, g_scratch);
    __half* qkv16 = (__half*)(g + OFF_QKV16);
    __half* rk16  = (__half*)(g + OFF_RK16);
    __half* cat16 = (__half*)(g + OFF_CAT16);
    __half* r16   = (__half*)(g + OFF_R16);
    __half* bd16  = (__half*)(g + OFF_BD16);
    __half* av16  = (__half*)(g + OFF_AV16);
    __half* wqkvt = (__half*)(g + OFF_WQKVT);
    __half* wrt   = (__half*)(g + OFF_WRT);
    __half* wot   = (__half*)(g + OFF_WOT);
    __half* vt16  = (__half*)(g + OFF_VT16);

    constexpr int SM128 = 3 * (128 + 128) * 72 * 2;   // 110,592 B
    constexpr int FLASH_SMEM = (128 * 72 + 3 * 128 * 72 + 3 * 64 * 136 + 3 * 256) * 2; // 127,488 B
    static bool attr_done = false;
    if (!attr_done) {
        cudaFuncSetAttribute((void*)gemm_h<128, float>,  cudaFuncAttributeMaxDynamicSharedMemorySize, SM128);
        cudaFuncSetAttribute((void*)gemm_h<128, __half>, cudaFuncAttributeMaxDynamicSharedMemorySize, SM128);
        cudaFuncSetAttribute((void*)flash_kernel, cudaFuncAttributeMaxDynamicSharedMemorySize, FLASH_SMEM);
        attr_done = true;
    }

    dim3 tb(32, 8);

    // 0) fp16 conversions + weight transposes
    cvt_cat<<<4096, 256>>>(mems, w, cat16);
    cvt_h<<<2048, 256>>>(r, r16);
    transpose_kh<<<dim3(96, 32), tb>>>(Wqkv, wqkvt, 1024, 3072);
    transpose_kh<<<dim3(32, 32), tb>>>(Wr,   wrt,   1024, 1024);
    transpose_kh<<<dim3(32, 32), tb>>>(Wo,   wot,   1024, 1024);

    // 1) QKV projection -> fp16
    gemm_h<128, __half><<<dim3(24, 32, 1), 256, SM128>>>(
        cat16, 1024, 0, 0,
        wqkvt, 1024, 0, 0,
        qkv16, 3072, 0, 0, 1024, 0, nullptr);

    // 2) R projection -> fp16
    gemm_h<128, __half><<<dim3(8, 16, 1), 256, SM128>>>(
        r16, 1024, 0, 0,
        wrt, 1024, 0, 0,
        rk16, 1024, 0, 0, 1024, 0, nullptr);

    // 3) rank-1 bias terms (acb for flash, bdb for BD epilogue)
    bias_dot<<<dim3(8192, 2), 256>>>(rwb, rrb);

    // 4) BD_pre = Q @ RK^T + bdb[col] -> fp16 (unused-tile skip)
    gemm_h<128, __half><<<dim3(16, 8, 32), 256, SM128>>>(
        qkv16 + 2048LL * 3072, 6144, 3072, 64,
        rk16,                  1024, 0,    64,
        bd16, 2048, 2097152LL, 4194304LL, 64, 2, g + OFF_BDB);

    // 5) V transpose -> fp16 [z][64][2048]
    vtrans_h<<<dim3(64, 2, 32), tb>>>(qkv16, vt16);

    // 6) fused attention: S + shift + bias + softmax + P@V
    flash_kernel<<<dim3(8, 32), 256, FLASH_SMEM>>>(
        qkv16, vt16, bd16, g + OFF_ACB, av16);

    // 7) output projection -> fp32
    gemm_h<128, float><<<dim3(8, 16, 1), 256, SM128>>>(
        av16, 1024, 0, 0,
        wot,  1024, 0, 0,
        g + OFF_AO, 1024, 0, 0, 1024, 0, nullptr);

    // 8) residual + LayerNorm
    ln_kernel<<<2048, 256>>>(w, gamma, beta, out);
}